// round 8
// baseline (speedup 1.0000x reference)
#include <cuda_runtime.h>
#include <cuda_fp16.h>
#include <cstdint>
#include <math.h>

// ---------------- problem constants ----------------
#define NTOK 4096      // B*T
#define DDIM 1024      // D
#define GNUM 4
#define FDIM 4096      // F
#define NEXP 16        // G*E
#define HROWS 10240    // 8192 pairs + per-expert 128-padding

// ---------------- GEMM tiling ----------------
#define BM 128
#define BN 128
#define BKH 64         // halves per K-tile (128 bytes = SW128 row)
#define STAGES 3
#define NTHREADS 128   // 4 warps (2x2), warp tile 64x64 -> 2 CTAs/SM

#define SM_TOK   0
#define SM_WT    512
#define SM_A     1024                      // STAGES x 16384
#define SM_B     (SM_A + STAGES * 16384)
#define SM_TOTAL (SM_B + STAGES * 16384)   // 99328 -> 2 CTAs/SM

// ---------------- device scratch ----------------
__device__ int    g_cnt[NEXP];
__device__ int    g_off[NEXP];
__device__ int    g_tok[NEXP][NTOK];
__device__ float  g_wt [NEXP][NTOK];
__device__ __half g_H  [(size_t)HROWS * FDIM];            // 80 MB
__device__ __half g_xh [(size_t)NTOK * DDIM];             // 8 MB
__device__ __half g_W1h[(size_t)NEXP * FDIM * DDIM];      // 128 MB
__device__ __half g_W2h[(size_t)NEXP * DDIM * FDIM];      // 128 MB

// ---------------- helpers ----------------
__device__ __forceinline__ uint32_t s2u(const void* p) {
    uint32_t a;
    asm("{ .reg .u64 t; cvta.to.shared.u64 t, %1; cvt.u32.u64 %0, t; }" : "=r"(a) : "l"(p));
    return a;
}
__device__ __forceinline__ float gelu_exact(float v) {
    return 0.5f * v * (1.0f + erff(v * 0.7071067811865476f));
}
__device__ __forceinline__ void mma_f16(float c[4], const uint32_t a[4],
                                        uint32_t b0, uint32_t b1) {
    asm volatile(
        "mma.sync.aligned.m16n8k16.row.col.f32.f16.f16.f32 "
        "{%0,%1,%2,%3}, {%4,%5,%6,%7}, {%8,%9}, {%0,%1,%2,%3};\n"
        : "+f"(c[0]), "+f"(c[1]), "+f"(c[2]), "+f"(c[3])
        : "r"(a[0]), "r"(a[1]), "r"(a[2]), "r"(a[3]), "r"(b0), "r"(b1));
}
__device__ __forceinline__ void ldsm4(uint32_t r[4], uint32_t addr) {
    asm volatile("ldmatrix.sync.aligned.m8n8.x4.shared.b16 {%0,%1,%2,%3}, [%4];"
        : "=r"(r[0]), "=r"(r[1]), "=r"(r[2]), "=r"(r[3]) : "r"(addr));
}
#define CP_ASYNC16(dst, src) \
    asm volatile("cp.async.cg.shared.global [%0], [%1], 16;" :: "r"(dst), "l"(src) : "memory")
#define CP_COMMIT() asm volatile("cp.async.commit_group;" ::: "memory")
#define CP_WAIT(n)  asm volatile("cp.async.wait_group %0;" :: "n"(n) : "memory")

// ---------------- kernel: f32 -> f16 conversion (prepass, weights) ----------
__global__ void cvt_kernel(const float* __restrict__ src, __half* __restrict__ dst, int n8) {
    int i = blockIdx.x * blockDim.x + threadIdx.x;
    int stride = gridDim.x * blockDim.x;
    for (; i < n8; i += stride) {
        const float4* s = (const float4*)src + (size_t)i * 2;
        float4 a = s[0], b = s[1];
        __half2 h0 = __floats2half2_rn(a.x, a.y);
        __half2 h1 = __floats2half2_rn(a.z, a.w);
        __half2 h2 = __floats2half2_rn(b.x, b.y);
        __half2 h3 = __floats2half2_rn(b.z, b.w);
        uint4 u;
        u.x = *(uint32_t*)&h0; u.y = *(uint32_t*)&h1;
        u.z = *(uint32_t*)&h2; u.w = *(uint32_t*)&h3;
        *((uint4*)dst + i) = u;
    }
}

// ---------------- kernel 0: zero expert counters ----------------
__global__ void zero_cnt_kernel() {
    if (threadIdx.x < NEXP) g_cnt[threadIdx.x] = 0;
}

// ---------------- kernel 1: routing (one warp per token) + x->fp16 ---------
__global__ void routing_kernel(const float* __restrict__ x,
                               const float* __restrict__ Wg,
                               const float* __restrict__ We,
                               float* __restrict__ out_logits,
                               float* __restrict__ out_ent) {
    int warp = (blockIdx.x * blockDim.x + threadIdx.x) >> 5;
    int lane = threadIdx.x & 31;
    if (warp >= NTOK) return;

    const float* xr = x + (size_t)warp * DDIM;
    __half* xhw = g_xh + (size_t)warp * DDIM;
    float acc[20];
#pragma unroll
    for (int j = 0; j < 20; j++) acc[j] = 0.f;

    for (int k = lane; k < DDIM; k += 32) {
        float xv = xr[k];
        xhw[k] = __float2half_rn(xv);          // fused x -> fp16
#pragma unroll
        for (int g = 0; g < GNUM; g++) acc[g] += xv * Wg[g * DDIM + k];
#pragma unroll
        for (int j = 0; j < NEXP; j++) acc[4 + j] += xv * We[j * DDIM + k];
    }
#pragma unroll
    for (int o = 16; o > 0; o >>= 1) {
#pragma unroll
        for (int j = 0; j < 20; j++) acc[j] += __shfl_xor_sync(0xFFFFFFFFu, acc[j], o);
    }

    if (lane == 0) {
        float gl[4] = {acc[0], acc[1], acc[2], acc[3]};
#pragma unroll
        for (int g = 0; g < 4; g++) out_logits[warp * 4 + g] = gl[g];

        float mx = fmaxf(fmaxf(gl[0], gl[1]), fmaxf(gl[2], gl[3]));
        float ex4[4], s = 0.f;
#pragma unroll
        for (int g = 0; g < 4; g++) { ex4[g] = expf(gl[g] - mx); s += ex4[g]; }
        float ls = logf(s);
        float ent = 0.f;
#pragma unroll
        for (int g = 0; g < 4; g++) {
            float p = ex4[g] / s;
            ent -= p * (gl[g] - mx - ls);
        }
        atomicAdd(out_ent, ent * (1.0f / NTOK));

        int g0 = 0;
#pragma unroll
        for (int g = 1; g < 4; g++) if (gl[g] > gl[g0]) g0 = g;
        int g1 = -1;
#pragma unroll
        for (int g = 0; g < 4; g++) {
            if (g == g0) continue;
            if (g1 < 0 || gl[g] > gl[g1]) g1 = g;
        }
        float w0 = 1.f / (1.f + expf(gl[g1] - gl[g0]));
        float w1 = 1.f - w0;

        int   gs[2] = {g0, g1};
        float ws[2] = {w0, w1};
#pragma unroll
        for (int i = 0; i < 2; i++) {
            int g = gs[i];
            int eb = 4 + g * 4;
            int e = 0;
#pragma unroll
            for (int e2 = 1; e2 < 4; e2++) if (acc[eb + e2] > acc[eb + e]) e = e2;
            int exid = g * 4 + e;
            int slot = atomicAdd(&g_cnt[exid], 1);
            g_tok[exid][slot] = warp;
            g_wt[exid][slot]  = ws[i];
        }
    }
}

// ---------------- kernel 2: 16-entry padded prefix scan ----------------
__global__ void scan_kernel() {
    if (threadIdx.x == 0) {
        int o = 0;
        for (int e = 0; e < NEXP; e++) {
            g_off[e] = o;
            o += (g_cnt[e] + 127) & ~127;
        }
    }
}

// ---------------- fp16 tensor-core GEMM ----------------
// C[m,n] = sum_k A[m,k]*B[n,k]  (both K-contiguous fp16 in gmem)
// 128 threads = 4 warps (2x2), warp tile 64x64, mma.m16n8k16, 2 CTAs/SM.
// Fragment double-buffering across the 4 kk16 steps of each K-tile.
// zbase: expert offset (expert-halved launches for cross-stream pipelining).
template <int KH, int SPLITK, bool FIRST>
__global__ void __launch_bounds__(NTHREADS, 2)
gemm_fp16(float* __restrict__ OUT, int zbase) {
    extern __shared__ char smem[];
    const int ex  = zbase + (int)blockIdx.z / SPLITK;
    const int ks  = (int)blockIdx.z % SPLITK;
    const int cnt = g_cnt[ex];
    const int m0  = blockIdx.y * BM;
    if (m0 >= cnt) return;
    const int n0  = blockIdx.x * BN;
    const int KHS = KH / SPLITK;
    const int kof = ks * KHS;

    const int tid  = threadIdx.x;
    const int wid  = tid >> 5;
    const int lane = tid & 31;
    const uint32_t sb = s2u(smem);

    int*   s_tok = (int*)(smem + SM_TOK);
    float* s_wt  = (float*)(smem + SM_WT);
    {
        int m  = m0 + tid;
        int mm = (m < cnt) ? m : (cnt - 1);
        s_tok[tid] = g_tok[ex][mm];
        s_wt[tid]  = (m < cnt) ? g_wt[ex][m] : 0.f;
    }
    __syncthreads();

    // ---- cp.async chunk assignment (16B chunks, SW128 swizzled dst) ----
    const __half* aSrc[8]; uint32_t aDst[8];
#pragma unroll
    for (int i = 0; i < 8; i++) {
        int c = tid + i * NTHREADS, r = c >> 3, u = c & 7;
        const __half* rowp;
        if (FIRST) rowp = g_xh + (size_t)s_tok[r] * DDIM;
        else       rowp = g_H  + (size_t)(g_off[ex] + m0 + r) * FDIM;
        aSrc[i] = rowp + kof + u * 8;
        aDst[i] = sb + SM_A + r * 128 + ((u ^ (r & 7)) << 4);
    }
    const __half* bSrc[8]; uint32_t bDst[8];
    const __half* Wb = (FIRST ? g_W1h : g_W2h) + (size_t)ex * ((size_t)FDIM * DDIM);
#pragma unroll
    for (int i = 0; i < 8; i++) {
        int c = tid + i * NTHREADS, r = c >> 3, u = c & 7;
        bSrc[i] = Wb + (size_t)(n0 + r) * KH + kof + u * 8;
        bDst[i] = sb + SM_B + r * 128 + ((u ^ (r & 7)) << 4);
    }

    auto issue_stage = [&](int kt, int s) {
        const uint32_t off = (uint32_t)s * 16384u;
#pragma unroll
        for (int i = 0; i < 8; i++) CP_ASYNC16(aDst[i] + off, aSrc[i] + (size_t)kt * BKH);
#pragma unroll
        for (int i = 0; i < 8; i++) CP_ASYNC16(bDst[i] + off, bSrc[i] + (size_t)kt * BKH);
        CP_COMMIT();
    };

    // ---- warp / lane geometry (2x2 warps, 64x64 each) ----
    const int wm = wid >> 1;
    const int wn = wid & 1;
    const int laRow = lane & 15;
    const int laDu  = (lane >> 4) & 1;
    const int lbRow = (lane & 7) + ((lane & 16) >> 1);
    const int lbDu  = (lane >> 3) & 1;

    float acc[4][8][4];
#pragma unroll
    for (int i = 0; i < 4; i++)
#pragma unroll
        for (int j = 0; j < 8; j++)
#pragma unroll
            for (int r = 0; r < 4; r++) acc[i][j][r] = 0.f;

    const int NKT = KHS / BKH;

    issue_stage(0, 0);
    issue_stage(1, 1);

    // double-buffered fragments
    uint32_t afr[2][4][4], bq[2][4][4];

    for (int kt = 0; kt < NKT; kt++) {
        if (kt + 1 < NKT) { CP_WAIT(1); } else { CP_WAIT(0); }
        __syncthreads();
        if (kt + 2 < NKT) issue_stage(kt + 2, (kt + 2) % STAGES);

        const int s = kt % STAGES;
        const uint32_t As = sb + SM_A + s * 16384;
        const uint32_t Bs = sb + SM_B + s * 16384;

        // load fragments for kk16 step 0 into buffer 0
#pragma unroll
        for (int fm = 0; fm < 4; fm++) {
            int r = wm * 64 + fm * 16 + laRow;
            ldsm4(afr[0][fm], As + r * 128 + ((laDu ^ (r & 7)) << 4));
        }
#pragma unroll
        for (int fp = 0; fp < 4; fp++) {
            int r = wn * 64 + fp * 16 + lbRow;
            ldsm4(bq[0][fp], Bs + r * 128 + ((lbDu ^ (r & 7)) << 4));
        }

#pragma unroll
        for (int kk = 0; kk < 4; kk++) {         // 4 kk16 steps / K-tile
            const int cur = kk & 1, nxt = cur ^ 1;
            if (kk < 3) {                         // prefetch next step's fragments
                const int ua = (kk + 1) * 2 + laDu;
                const int ub = (kk + 1) * 2 + lbDu;
#pragma unroll
                for (int fm = 0; fm < 4; fm++) {
                    int r = wm * 64 + fm * 16 + laRow;
                    ldsm4(afr[nxt][fm], As + r * 128 + ((ua ^ (r & 7)) << 4));
                }
#pragma unroll
                for (int fp = 0; fp < 4; fp++) {
                    int r = wn * 64 + fp * 16 + lbRow;
                    ldsm4(bq[nxt][fp], Bs + r * 128 + ((ub ^ (r & 7)) << 4));
                }
            }
#pragma unroll
            for (int fm = 0; fm < 4; fm++)
#pragma unroll
                for (int fp = 0; fp < 4; fp++) {
                    mma_f16(acc[fm][2 * fp],     afr[cur][fm], bq[cur][fp][0], bq[cur][fp][1]);
                    mma_f16(acc[fm][2 * fp + 1], afr[cur][fm], bq[cur][fp][2], bq[cur][fp][3]);
                }
        }
        // no trailing barrier: next iteration's top barrier fences reuse
    }

    // ---------------- epilogue ----------------
    const int er = lane >> 2;
    const int ec = (lane & 3) * 2;
    if (FIRST) {
        const int hb = g_off[ex];
#pragma unroll
        for (int fm = 0; fm < 4; fm++) {
#pragma unroll
            for (int hh = 0; hh < 2; hh++) {
                int mloc = wm * 64 + fm * 16 + er + hh * 8;
                int m = m0 + mloc;
                if (m < cnt) {
                    __half* dst = g_H + (size_t)(hb + m) * FDIM + n0 + wn * 64 + ec;
#pragma unroll
                    for (int fn = 0; fn < 8; fn++) {
                        float v0 = gelu_exact(acc[fm][fn][hh * 2 + 0]);
                        float v1 = gelu_exact(acc[fm][fn][hh * 2 + 1]);
                        *(__half2*)(dst + fn * 8) = __floats2half2_rn(v0, v1);
                    }
                }
            }
        }
    } else {
#pragma unroll
        for (int fm = 0; fm < 4; fm++) {
#pragma unroll
            for (int hh = 0; hh < 2; hh++) {
                int mloc = wm * 64 + fm * 16 + er + hh * 8;
                int m = m0 + mloc;
                if (m < cnt) {
                    int   tok = s_tok[mloc];
                    float w   = s_wt[mloc];
                    float* dst = OUT + (size_t)tok * DDIM + n0 + wn * 64 + ec;
#pragma unroll
                    for (int fn = 0; fn < 8; fn++) {
                        atomicAdd(dst + fn * 8 + 0, w * acc[fm][fn][hh * 2 + 0]);
                        atomicAdd(dst + fn * 8 + 1, w * acc[fm][fn][hh * 2 + 1]);
                    }
                }
            }
        }
    }
}

// ---------------- launch ----------------
extern "C" void kernel_launch(void* const* d_in, const int* in_sizes, int n_in,
                              void* d_out, int out_size) {
    const float* x  = (const float*)d_in[0];
    const float* Wg = (const float*)d_in[1];
    const float* We = (const float*)d_in[2];
    const float* W1 = (const float*)d_in[3];
    const float* W2 = (const float*)d_in[4];
    float* out = (float*)d_out;

    // output layout: [out (N*D)] [group_logits (N*G)] [group_entropy (1)]
    float* out_logits = out + (size_t)NTOK * DDIM;
    float* out_ent    = out_logits + (size_t)NTOK * GNUM;

    static __half* w1h_p = nullptr;
    static __half* w2h_p = nullptr;
    static cudaStream_t s1, s2;
    static cudaEvent_t eFork, eCvt1, eCvt2, eG1a, eG2a;
    if (!w1h_p) {
        cudaGetSymbolAddress((void**)&w1h_p, g_W1h);
        cudaGetSymbolAddress((void**)&w2h_p, g_W2h);
        cudaFuncSetAttribute((const void*)gemm_fp16<DDIM, 1, true>,
                             cudaFuncAttributeMaxDynamicSharedMemorySize, SM_TOTAL);
        cudaFuncSetAttribute((const void*)gemm_fp16<FDIM, 2, false>,
                             cudaFuncAttributeMaxDynamicSharedMemorySize, SM_TOTAL);
        cudaStreamCreateWithFlags(&s1, cudaStreamNonBlocking);
        cudaStreamCreateWithFlags(&s2, cudaStreamNonBlocking);
        cudaEventCreateWithFlags(&eFork, cudaEventDisableTiming);
        cudaEventCreateWithFlags(&eCvt1, cudaEventDisableTiming);
        cudaEventCreateWithFlags(&eCvt2, cudaEventDisableTiming);
        cudaEventCreateWithFlags(&eG1a, cudaEventDisableTiming);
        cudaEventCreateWithFlags(&eG2a, cudaEventDisableTiming);
    }

    // --- fork: side streams convert weights while stream 0 routes ---
    cudaMemsetAsync(d_out, 0, (size_t)out_size * sizeof(float), 0);
    zero_cnt_kernel<<<1, 32>>>();
    cudaEventRecord(eFork, 0);
    cudaStreamWaitEvent(s1, eFork, 0);
    cudaStreamWaitEvent(s2, eFork, 0);

    cvt_kernel<<<2048, 256, 0, s1>>>(W1, w1h_p, NEXP * FDIM * DDIM / 8);
    cudaEventRecord(eCvt1, s1);

    cvt_kernel<<<2048, 256, 0, s2>>>(W2, w2h_p, NEXP * DDIM * FDIM / 8);
    cudaEventRecord(eCvt2, s2);

    routing_kernel<<<(NTOK * 32 + 255) / 256, 256>>>(x, Wg, We, out_logits, out_ent);
    scan_kernel<<<1, 32>>>();

    // --- GEMM1 in two expert halves; GEMM2 first half pipelined on s2 ---
    cudaStreamWaitEvent(0, eCvt1, 0);
    dim3 g1(FDIM / BN, NTOK / BM, NEXP / 2);
    gemm_fp16<DDIM, 1, true><<<g1, NTHREADS, SM_TOTAL>>>(nullptr, 0);
    cudaEventRecord(eG1a, 0);
    gemm_fp16<DDIM, 1, true><<<g1, NTHREADS, SM_TOTAL>>>(nullptr, 8);

    // s2 already holds cvt W2; chain G2a (experts 0..7) after G1a
    cudaStreamWaitEvent(s2, eG1a, 0);
    dim3 g2(DDIM / BN, NTOK / BM, (NEXP / 2) * 2);
    gemm_fp16<FDIM, 2, false><<<g2, NTHREADS, SM_TOTAL, s2>>>(out, 0);
    cudaEventRecord(eG2a, s2);

    // stream 0: G2b (experts 8..15) after G1b (program order) + cvt W2
    cudaStreamWaitEvent(0, eCvt2, 0);
    gemm_fp16<FDIM, 2, false><<<g2, NTHREADS, SM_TOTAL>>>(out, 8);

    // final join
    cudaStreamWaitEvent(0, eG2a, 0);
}

// round 10
// speedup vs baseline: 1.3592x; 1.3592x over previous
#include <cuda_runtime.h>
#include <cuda_fp16.h>
#include <cstdint>
#include <math.h>

// ---------------- problem constants ----------------
#define NTOK 4096      // B*T
#define DDIM 1024      // D
#define GNUM 4
#define FDIM 4096      // F
#define NEXP 16        // G*E
#define HROWS 10240    // 8192 pairs + per-expert 128-padding

// ---------------- GEMM tiling ----------------
#define BM 128
#define BN 128
#define BKH 64         // halves per K-tile (128 bytes = SW128 row)
#define STAGES 3
#define NTHREADS 128   // 4 warps (2x2), warp tile 64x64 -> 2 CTAs/SM

#define SM_TOK   0
#define SM_WT    512
#define SM_A     1024                      // STAGES x 16384
#define SM_B     (SM_A + STAGES * 16384)
#define SM_TOTAL (SM_B + STAGES * 16384)   // 99328 -> 2 CTAs/SM

// ---------------- device scratch ----------------
__device__ int    g_cnt[NEXP];
__device__ int    g_off[NEXP];
__device__ int    g_tok[NEXP][NTOK];
__device__ float  g_wt [NEXP][NTOK];
__device__ __half g_H  [(size_t)HROWS * FDIM];            // 80 MB
__device__ __half g_xh [(size_t)NTOK * DDIM];             // 8 MB
__device__ __half g_W1h[(size_t)NEXP * FDIM * DDIM];      // 128 MB
__device__ __half g_W2h[(size_t)NEXP * DDIM * FDIM];      // 128 MB

// ---------------- helpers ----------------
__device__ __forceinline__ uint32_t s2u(const void* p) {
    uint32_t a;
    asm("{ .reg .u64 t; cvta.to.shared.u64 t, %1; cvt.u32.u64 %0, t; }" : "=r"(a) : "l"(p));
    return a;
}
__device__ __forceinline__ float gelu_exact(float v) {
    return 0.5f * v * (1.0f + erff(v * 0.7071067811865476f));
}
__device__ __forceinline__ void mma_f16(float c[4], const uint32_t a[4], const uint32_t b[2]) {
    asm volatile(
        "mma.sync.aligned.m16n8k16.row.col.f32.f16.f16.f32 "
        "{%0,%1,%2,%3}, {%4,%5,%6,%7}, {%8,%9}, {%0,%1,%2,%3};\n"
        : "+f"(c[0]), "+f"(c[1]), "+f"(c[2]), "+f"(c[3])
        : "r"(a[0]), "r"(a[1]), "r"(a[2]), "r"(a[3]), "r"(b[0]), "r"(b[1]));
}
__device__ __forceinline__ void ldsm4(uint32_t r[4], uint32_t addr) {
    asm volatile("ldmatrix.sync.aligned.m8n8.x4.shared.b16 {%0,%1,%2,%3}, [%4];"
        : "=r"(r[0]), "=r"(r[1]), "=r"(r[2]), "=r"(r[3]) : "r"(addr));
}
#define CP_ASYNC16(dst, src) \
    asm volatile("cp.async.cg.shared.global [%0], [%1], 16;" :: "r"(dst), "l"(src) : "memory")
#define CP_COMMIT() asm volatile("cp.async.commit_group;" ::: "memory")
#define CP_WAIT(n)  asm volatile("cp.async.wait_group %0;" :: "n"(n) : "memory")

// ---------------- kernel: f32 -> f16 conversion (prepass) ----------------
__global__ void cvt_kernel(const float* __restrict__ src, __half* __restrict__ dst, int n8) {
    int i = blockIdx.x * blockDim.x + threadIdx.x;
    int stride = gridDim.x * blockDim.x;
    for (; i < n8; i += stride) {
        const float4* s = (const float4*)src + (size_t)i * 2;
        float4 a = s[0], b = s[1];
        __half2 h0 = __floats2half2_rn(a.x, a.y);
        __half2 h1 = __floats2half2_rn(a.z, a.w);
        __half2 h2 = __floats2half2_rn(b.x, b.y);
        __half2 h3 = __floats2half2_rn(b.z, b.w);
        uint4 u;
        u.x = *(uint32_t*)&h0; u.y = *(uint32_t*)&h1;
        u.z = *(uint32_t*)&h2; u.w = *(uint32_t*)&h3;
        *((uint4*)dst + i) = u;
    }
}

// ---------------- kernel 0: zero expert counters ----------------
__global__ void zero_cnt_kernel() {
    if (threadIdx.x < NEXP) g_cnt[threadIdx.x] = 0;
}

// ---------------- kernel 1: routing (one warp per token) ----------------
__global__ void routing_kernel(const float* __restrict__ x,
                               const float* __restrict__ Wg,
                               const float* __restrict__ We,
                               float* __restrict__ out_logits,
                               float* __restrict__ out_ent) {
    int warp = (blockIdx.x * blockDim.x + threadIdx.x) >> 5;
    int lane = threadIdx.x & 31;
    if (warp >= NTOK) return;

    const float* xr = x + (size_t)warp * DDIM;
    float acc[20];
#pragma unroll
    for (int j = 0; j < 20; j++) acc[j] = 0.f;

    for (int k = lane; k < DDIM; k += 32) {
        float xv = xr[k];
#pragma unroll
        for (int g = 0; g < GNUM; g++) acc[g] += xv * Wg[g * DDIM + k];
#pragma unroll
        for (int j = 0; j < NEXP; j++) acc[4 + j] += xv * We[j * DDIM + k];
    }
#pragma unroll
    for (int o = 16; o > 0; o >>= 1) {
#pragma unroll
        for (int j = 0; j < 20; j++) acc[j] += __shfl_xor_sync(0xFFFFFFFFu, acc[j], o);
    }

    if (lane == 0) {
        float gl[4] = {acc[0], acc[1], acc[2], acc[3]};
#pragma unroll
        for (int g = 0; g < 4; g++) out_logits[warp * 4 + g] = gl[g];

        float mx = fmaxf(fmaxf(gl[0], gl[1]), fmaxf(gl[2], gl[3]));
        float ex4[4], s = 0.f;
#pragma unroll
        for (int g = 0; g < 4; g++) { ex4[g] = expf(gl[g] - mx); s += ex4[g]; }
        float ls = logf(s);
        float ent = 0.f;
#pragma unroll
        for (int g = 0; g < 4; g++) {
            float p = ex4[g] / s;
            ent -= p * (gl[g] - mx - ls);
        }
        atomicAdd(out_ent, ent * (1.0f / NTOK));

        int g0 = 0;
#pragma unroll
        for (int g = 1; g < 4; g++) if (gl[g] > gl[g0]) g0 = g;
        int g1 = -1;
#pragma unroll
        for (int g = 0; g < 4; g++) {
            if (g == g0) continue;
            if (g1 < 0 || gl[g] > gl[g1]) g1 = g;
        }
        float w0 = 1.f / (1.f + expf(gl[g1] - gl[g0]));
        float w1 = 1.f - w0;

        int   gs[2] = {g0, g1};
        float ws[2] = {w0, w1};
#pragma unroll
        for (int i = 0; i < 2; i++) {
            int g = gs[i];
            int eb = 4 + g * 4;
            int e = 0;
#pragma unroll
            for (int e2 = 1; e2 < 4; e2++) if (acc[eb + e2] > acc[eb + e]) e = e2;
            int exid = g * 4 + e;
            int slot = atomicAdd(&g_cnt[exid], 1);
            g_tok[exid][slot] = warp;
            g_wt[exid][slot]  = ws[i];
        }
    }
}

// ---------------- kernel 2: 16-entry padded prefix scan ----------------
__global__ void scan_kernel() {
    if (threadIdx.x == 0) {
        int o = 0;
        for (int e = 0; e < NEXP; e++) {
            g_off[e] = o;
            o += (g_cnt[e] + 127) & ~127;
        }
    }
}

// ---------------- fp16 tensor-core GEMM (R7 mainloop, +zbase) --------------
// C[m,n] = sum_k A[m,k]*B[n,k]  (both K-contiguous fp16 in gmem)
// FIRST=true : A = gathered x (fp16), B = W1h[ex], epilogue gelu -> g_H (fp16)
// FIRST=false: A = g_H rows,         B = W2h[ex], epilogue w * atomicAdd -> out (f32)
// 128 threads = 4 warps (2x2), warp tile 64x64, mma.m16n8k16, 2 CTAs/SM
template <int KH, int SPLITK, bool FIRST>
__global__ void __launch_bounds__(NTHREADS, 2)
gemm_fp16(float* __restrict__ OUT, int zbase) {
    extern __shared__ char smem[];
    const int ex  = zbase + (int)blockIdx.z / SPLITK;
    const int ks  = (int)blockIdx.z % SPLITK;
    const int cnt = g_cnt[ex];
    const int m0  = blockIdx.y * BM;
    if (m0 >= cnt) return;
    const int n0  = blockIdx.x * BN;
    const int KHS = KH / SPLITK;
    const int kof = ks * KHS;

    const int tid  = threadIdx.x;
    const int wid  = tid >> 5;
    const int lane = tid & 31;
    const uint32_t sb = s2u(smem);

    int*   s_tok = (int*)(smem + SM_TOK);
    float* s_wt  = (float*)(smem + SM_WT);
    {
        int m  = m0 + tid;
        int mm = (m < cnt) ? m : (cnt - 1);
        s_tok[tid] = g_tok[ex][mm];
        s_wt[tid]  = (m < cnt) ? g_wt[ex][m] : 0.f;
    }
    __syncthreads();

    // ---- cp.async chunk assignment (16B chunks, SW128 swizzled dst) ----
    const __half* aSrc[8]; uint32_t aDst[8];
#pragma unroll
    for (int i = 0; i < 8; i++) {
        int c = tid + i * NTHREADS, r = c >> 3, u = c & 7;
        const __half* rowp;
        if (FIRST) rowp = g_xh + (size_t)s_tok[r] * DDIM;
        else       rowp = g_H  + (size_t)(g_off[ex] + m0 + r) * FDIM;
        aSrc[i] = rowp + kof + u * 8;
        aDst[i] = sb + SM_A + r * 128 + ((u ^ (r & 7)) << 4);
    }
    const __half* bSrc[8]; uint32_t bDst[8];
    const __half* Wb = (FIRST ? g_W1h : g_W2h) + (size_t)ex * ((size_t)FDIM * DDIM);
#pragma unroll
    for (int i = 0; i < 8; i++) {
        int c = tid + i * NTHREADS, r = c >> 3, u = c & 7;
        bSrc[i] = Wb + (size_t)(n0 + r) * KH + kof + u * 8;
        bDst[i] = sb + SM_B + r * 128 + ((u ^ (r & 7)) << 4);
    }

    auto issue_stage = [&](int kt, int s) {
        const uint32_t off = (uint32_t)s * 16384u;
#pragma unroll
        for (int i = 0; i < 8; i++) CP_ASYNC16(aDst[i] + off, aSrc[i] + (size_t)kt * BKH);
#pragma unroll
        for (int i = 0; i < 8; i++) CP_ASYNC16(bDst[i] + off, bSrc[i] + (size_t)kt * BKH);
        CP_COMMIT();
    };

    // ---- warp / lane geometry (2x2 warps, 64x64 each) ----
    const int wm = wid >> 1;
    const int wn = wid & 1;
    const int laRow = lane & 15;
    const int laDu  = (lane >> 4) & 1;
    const int lbRow = (lane & 7) + ((lane & 16) >> 1);
    const int lbDu  = (lane >> 3) & 1;

    float acc[4][8][4];
#pragma unroll
    for (int i = 0; i < 4; i++)
#pragma unroll
        for (int j = 0; j < 8; j++)
#pragma unroll
            for (int r = 0; r < 4; r++) acc[i][j][r] = 0.f;

    const int NKT = KHS / BKH;

    issue_stage(0, 0);
    issue_stage(1, 1);

    for (int kt = 0; kt < NKT; kt++) {
        if (kt + 1 < NKT) { CP_WAIT(1); } else { CP_WAIT(0); }
        __syncthreads();
        // safe post-barrier prefetch: stage (kt+2)%3 was last read in iter kt-1
        if (kt + 2 < NKT) issue_stage(kt + 2, (kt + 2) % STAGES);

        const int s = kt % STAGES;
        const uint32_t As = sb + SM_A + s * 16384;
        const uint32_t Bs = sb + SM_B + s * 16384;

#pragma unroll
        for (int kk8 = 0; kk8 < 8; kk8 += 2) {   // 4 kk16 steps per K-tile
            uint32_t afr[4][4], bfr[8][2];
#pragma unroll
            for (int fm = 0; fm < 4; fm++) {
                int r = wm * 64 + fm * 16 + laRow;
                int u = kk8 + laDu;
                ldsm4(afr[fm], As + r * 128 + ((u ^ (r & 7)) << 4));
            }
#pragma unroll
            for (int fp = 0; fp < 4; fp++) {
                int r = wn * 64 + fp * 16 + lbRow;
                int u = kk8 + lbDu;
                uint32_t q[4];
                ldsm4(q, Bs + r * 128 + ((u ^ (r & 7)) << 4));
                bfr[2 * fp][0] = q[0]; bfr[2 * fp][1] = q[1];
                bfr[2 * fp + 1][0] = q[2]; bfr[2 * fp + 1][1] = q[3];
            }
#pragma unroll
            for (int fm = 0; fm < 4; fm++)
#pragma unroll
                for (int fn = 0; fn < 8; fn++)
                    mma_f16(acc[fm][fn], afr[fm], bfr[fn]);
        }
        // no trailing barrier: next iteration's top barrier fences reuse
    }

    // ---------------- epilogue ----------------
    const int er = lane >> 2;
    const int ec = (lane & 3) * 2;
    if (FIRST) {
        const int hb = g_off[ex];
#pragma unroll
        for (int fm = 0; fm < 4; fm++) {
#pragma unroll
            for (int hh = 0; hh < 2; hh++) {
                int mloc = wm * 64 + fm * 16 + er + hh * 8;
                int m = m0 + mloc;
                if (m < cnt) {
                    __half* dst = g_H + (size_t)(hb + m) * FDIM + n0 + wn * 64 + ec;
#pragma unroll
                    for (int fn = 0; fn < 8; fn++) {
                        float v0 = gelu_exact(acc[fm][fn][hh * 2 + 0]);
                        float v1 = gelu_exact(acc[fm][fn][hh * 2 + 1]);
                        *(__half2*)(dst + fn * 8) = __floats2half2_rn(v0, v1);
                    }
                }
            }
        }
    } else {
#pragma unroll
        for (int fm = 0; fm < 4; fm++) {
#pragma unroll
            for (int hh = 0; hh < 2; hh++) {
                int mloc = wm * 64 + fm * 16 + er + hh * 8;
                int m = m0 + mloc;
                if (m < cnt) {
                    int   tok = s_tok[mloc];
                    float w   = s_wt[mloc];
                    float* dst = OUT + (size_t)tok * DDIM + n0 + wn * 64 + ec;
#pragma unroll
                    for (int fn = 0; fn < 8; fn++) {
                        atomicAdd(dst + fn * 8 + 0, w * acc[fm][fn][hh * 2 + 0]);
                        atomicAdd(dst + fn * 8 + 1, w * acc[fm][fn][hh * 2 + 1]);
                    }
                }
            }
        }
    }
}

// ---------------- launch ----------------
extern "C" void kernel_launch(void* const* d_in, const int* in_sizes, int n_in,
                              void* d_out, int out_size) {
    const float* x  = (const float*)d_in[0];
    const float* Wg = (const float*)d_in[1];
    const float* We = (const float*)d_in[2];
    const float* W1 = (const float*)d_in[3];
    const float* W2 = (const float*)d_in[4];
    float* out = (float*)d_out;

    // output layout: [out (N*D)] [group_logits (N*G)] [group_entropy (1)]
    float* out_logits = out + (size_t)NTOK * DDIM;
    float* out_ent    = out_logits + (size_t)NTOK * GNUM;

    static __half* xh_p  = nullptr;
    static __half* w1h_p = nullptr;
    static __half* w2h_p = nullptr;
    static cudaStream_t s1, s2;
    static cudaEvent_t eFork, eCvt1, eCvt2, eG1a, eG2a;
    if (!xh_p) {
        cudaGetSymbolAddress((void**)&xh_p,  g_xh);
        cudaGetSymbolAddress((void**)&w1h_p, g_W1h);
        cudaGetSymbolAddress((void**)&w2h_p, g_W2h);
        cudaFuncSetAttribute((const void*)gemm_fp16<DDIM, 1, true>,
                             cudaFuncAttributeMaxDynamicSharedMemorySize, SM_TOTAL);
        cudaFuncSetAttribute((const void*)gemm_fp16<FDIM, 2, false>,
                             cudaFuncAttributeMaxDynamicSharedMemorySize, SM_TOTAL);
        cudaStreamCreateWithFlags(&s1, cudaStreamNonBlocking);
        cudaStreamCreateWithFlags(&s2, cudaStreamNonBlocking);
        cudaEventCreateWithFlags(&eFork, cudaEventDisableTiming);
        cudaEventCreateWithFlags(&eCvt1, cudaEventDisableTiming);
        cudaEventCreateWithFlags(&eCvt2, cudaEventDisableTiming);
        cudaEventCreateWithFlags(&eG1a, cudaEventDisableTiming);
        cudaEventCreateWithFlags(&eG2a, cudaEventDisableTiming);
    }

    // --- fork: side streams do the fp16 conversions while stream 0 routes ---
    cudaMemsetAsync(d_out, 0, (size_t)out_size * sizeof(float), 0);
    zero_cnt_kernel<<<1, 32>>>();
    cudaEventRecord(eFork, 0);
    cudaStreamWaitEvent(s1, eFork, 0);
    cudaStreamWaitEvent(s2, eFork, 0);

    cvt_kernel<<<512, 256, 0, s1>>>(x,  xh_p,  NTOK * DDIM / 8);
    cvt_kernel<<<2048, 256, 0, s1>>>(W1, w1h_p, NEXP * FDIM * DDIM / 8);
    cudaEventRecord(eCvt1, s1);

    cvt_kernel<<<2048, 256, 0, s2>>>(W2, w2h_p, NEXP * DDIM * FDIM / 8);
    cudaEventRecord(eCvt2, s2);

    routing_kernel<<<(NTOK * 32 + 255) / 256, 256>>>(x, Wg, We, out_logits, out_ent);
    scan_kernel<<<1, 32>>>();

    // --- GEMM1 in two expert halves on stream 0 ---
    cudaStreamWaitEvent(0, eCvt1, 0);
    dim3 g1(FDIM / BN, NTOK / BM, NEXP / 2);
    gemm_fp16<DDIM, 1, true><<<g1, NTHREADS, SM_TOTAL>>>(nullptr, 0);
    cudaEventRecord(eG1a, 0);
    gemm_fp16<DDIM, 1, true><<<g1, NTHREADS, SM_TOTAL>>>(nullptr, 8);

    // --- s2: G2a (experts 0..7) overlaps G1b; needs cvt W2 (program order on s2) + G1a ---
    cudaStreamWaitEvent(s2, eG1a, 0);
    dim3 g2(DDIM / BN, NTOK / BM, (NEXP / 2) * 2);
    gemm_fp16<FDIM, 2, false><<<g2, NTHREADS, SM_TOTAL, s2>>>(out, 0);
    cudaEventRecord(eG2a, s2);

    // --- stream 0: G2b (experts 8..15) after G1b (program order) + cvt W2 ---
    cudaStreamWaitEvent(0, eCvt2, 0);
    gemm_fp16<FDIM, 2, false><<<g2, NTHREADS, SM_TOTAL>>>(out, 8);

    // final join
    cudaStreamWaitEvent(0, eG2a, 0);
}

// round 11
// speedup vs baseline: 1.3872x; 1.0206x over previous
#include <cuda_runtime.h>
#include <cuda_fp16.h>
#include <cstdint>
#include <math.h>

// ---------------- problem constants ----------------
#define NTOK 4096      // B*T
#define DDIM 1024      // D
#define GNUM 4
#define FDIM 4096      // F
#define NEXP 16        // G*E
#define HROWS 10240    // 8192 pairs + per-expert 128-padding

// ---------------- GEMM tiling ----------------
#define BM 128
#define BN 128
#define BKH 64         // halves per K-tile (128 bytes = SW128 row)
#define STAGES 3
#define NTHREADS 128   // 4 warps (2x2), warp tile 64x64 -> 2 CTAs/SM

#define SM_TOK   0
#define SM_WT    512
#define SM_A     1024                      // STAGES x 16384
#define SM_B     (SM_A + STAGES * 16384)
#define SM_TOTAL (SM_B + STAGES * 16384)   // 99328 -> 2 CTAs/SM

// ---------------- device scratch ----------------
__device__ int    g_cnt[NEXP];
__device__ int    g_off[NEXP];
__device__ int    g_tok[NEXP][NTOK];
__device__ float  g_wt [NEXP][NTOK];
__device__ __half g_H  [(size_t)HROWS * FDIM];            // 80 MB
__device__ __half g_xh [(size_t)NTOK * DDIM];             // 8 MB
__device__ __half g_W1h[(size_t)NEXP * FDIM * DDIM];      // 128 MB
__device__ __half g_W2h[(size_t)NEXP * DDIM * FDIM];      // 128 MB

// ---------------- helpers ----------------
__device__ __forceinline__ uint32_t s2u(const void* p) {
    uint32_t a;
    asm("{ .reg .u64 t; cvta.to.shared.u64 t, %1; cvt.u32.u64 %0, t; }" : "=r"(a) : "l"(p));
    return a;
}
__device__ __forceinline__ float gelu_exact(float v) {
    return 0.5f * v * (1.0f + erff(v * 0.7071067811865476f));
}
__device__ __forceinline__ void mma_f16(float c[4], const uint32_t a[4], const uint32_t b[2]) {
    asm volatile(
        "mma.sync.aligned.m16n8k16.row.col.f32.f16.f16.f32 "
        "{%0,%1,%2,%3}, {%4,%5,%6,%7}, {%8,%9}, {%0,%1,%2,%3};\n"
        : "+f"(c[0]), "+f"(c[1]), "+f"(c[2]), "+f"(c[3])
        : "r"(a[0]), "r"(a[1]), "r"(a[2]), "r"(a[3]), "r"(b[0]), "r"(b[1]));
}
__device__ __forceinline__ void ldsm4(uint32_t r[4], uint32_t addr) {
    asm volatile("ldmatrix.sync.aligned.m8n8.x4.shared.b16 {%0,%1,%2,%3}, [%4];"
        : "=r"(r[0]), "=r"(r[1]), "=r"(r[2]), "=r"(r[3]) : "r"(addr));
}
#define CP_ASYNC16(dst, src) \
    asm volatile("cp.async.cg.shared.global [%0], [%1], 16;" :: "r"(dst), "l"(src) : "memory")
#define CP_COMMIT() asm volatile("cp.async.commit_group;" ::: "memory")
#define CP_WAIT(n)  asm volatile("cp.async.wait_group %0;" :: "n"(n) : "memory")

// ---------------- kernel: f32 -> f16 conversion (prepass) ----------------
__global__ void cvt_kernel(const float* __restrict__ src, __half* __restrict__ dst, int n8) {
    int i = blockIdx.x * blockDim.x + threadIdx.x;
    int stride = gridDim.x * blockDim.x;
    for (; i < n8; i += stride) {
        const float4* s = (const float4*)src + (size_t)i * 2;
        float4 a = s[0], b = s[1];
        __half2 h0 = __floats2half2_rn(a.x, a.y);
        __half2 h1 = __floats2half2_rn(a.z, a.w);
        __half2 h2 = __floats2half2_rn(b.x, b.y);
        __half2 h3 = __floats2half2_rn(b.z, b.w);
        uint4 u;
        u.x = *(uint32_t*)&h0; u.y = *(uint32_t*)&h1;
        u.z = *(uint32_t*)&h2; u.w = *(uint32_t*)&h3;
        *((uint4*)dst + i) = u;
    }
}

// ---------------- kernel 0: zero expert counters ----------------
__global__ void zero_cnt_kernel() {
    if (threadIdx.x < NEXP) g_cnt[threadIdx.x] = 0;
}

// ---------------- kernel 1: routing (one warp per token) ----------------
__global__ void routing_kernel(const float* __restrict__ x,
                               const float* __restrict__ Wg,
                               const float* __restrict__ We,
                               float* __restrict__ out_logits,
                               float* __restrict__ out_ent) {
    int warp = (blockIdx.x * blockDim.x + threadIdx.x) >> 5;
    int lane = threadIdx.x & 31;
    if (warp >= NTOK) return;

    const float* xr = x + (size_t)warp * DDIM;
    float acc[20];
#pragma unroll
    for (int j = 0; j < 20; j++) acc[j] = 0.f;

    for (int k = lane; k < DDIM; k += 32) {
        float xv = xr[k];
#pragma unroll
        for (int g = 0; g < GNUM; g++) acc[g] += xv * Wg[g * DDIM + k];
#pragma unroll
        for (int j = 0; j < NEXP; j++) acc[4 + j] += xv * We[j * DDIM + k];
    }
#pragma unroll
    for (int o = 16; o > 0; o >>= 1) {
#pragma unroll
        for (int j = 0; j < 20; j++) acc[j] += __shfl_xor_sync(0xFFFFFFFFu, acc[j], o);
    }

    if (lane == 0) {
        float gl[4] = {acc[0], acc[1], acc[2], acc[3]};
#pragma unroll
        for (int g = 0; g < 4; g++) out_logits[warp * 4 + g] = gl[g];

        float mx = fmaxf(fmaxf(gl[0], gl[1]), fmaxf(gl[2], gl[3]));
        float ex4[4], s = 0.f;
#pragma unroll
        for (int g = 0; g < 4; g++) { ex4[g] = expf(gl[g] - mx); s += ex4[g]; }
        float ls = logf(s);
        float ent = 0.f;
#pragma unroll
        for (int g = 0; g < 4; g++) {
            float p = ex4[g] / s;
            ent -= p * (gl[g] - mx - ls);
        }
        atomicAdd(out_ent, ent * (1.0f / NTOK));

        int g0 = 0;
#pragma unroll
        for (int g = 1; g < 4; g++) if (gl[g] > gl[g0]) g0 = g;
        int g1 = -1;
#pragma unroll
        for (int g = 0; g < 4; g++) {
            if (g == g0) continue;
            if (g1 < 0 || gl[g] > gl[g1]) g1 = g;
        }
        float w0 = 1.f / (1.f + expf(gl[g1] - gl[g0]));
        float w1 = 1.f - w0;

        int   gs[2] = {g0, g1};
        float ws[2] = {w0, w1};
#pragma unroll
        for (int i = 0; i < 2; i++) {
            int g = gs[i];
            int eb = 4 + g * 4;
            int e = 0;
#pragma unroll
            for (int e2 = 1; e2 < 4; e2++) if (acc[eb + e2] > acc[eb + e]) e = e2;
            int exid = g * 4 + e;
            int slot = atomicAdd(&g_cnt[exid], 1);
            g_tok[exid][slot] = warp;
            g_wt[exid][slot]  = ws[i];
        }
    }
}

// ---------------- kernel 2: 16-entry padded prefix scan ----------------
__global__ void scan_kernel() {
    if (threadIdx.x == 0) {
        int o = 0;
        for (int e = 0; e < NEXP; e++) {
            g_off[e] = o;
            o += (g_cnt[e] + 127) & ~127;
        }
    }
}

// ---------------- fp16 tensor-core GEMM (R7 mainloop, +zbase) --------------
// C[m,n] = sum_k A[m,k]*B[n,k]  (both K-contiguous fp16 in gmem)
// FIRST=true : A = gathered x (fp16), B = W1h[ex], epilogue gelu -> g_H (fp16)
// FIRST=false: A = g_H rows,         B = W2h[ex], epilogue w * atomicAdd -> out (f32)
// 128 threads = 4 warps (2x2), warp tile 64x64, mma.m16n8k16, 2 CTAs/SM
template <int KH, int SPLITK, bool FIRST>
__global__ void __launch_bounds__(NTHREADS, 2)
gemm_fp16(float* __restrict__ OUT, int zbase) {
    extern __shared__ char smem[];
    const int ex  = zbase + (int)blockIdx.z / SPLITK;
    const int ks  = (int)blockIdx.z % SPLITK;
    const int cnt = g_cnt[ex];
    const int m0  = blockIdx.y * BM;
    if (m0 >= cnt) return;
    const int n0  = blockIdx.x * BN;
    const int KHS = KH / SPLITK;
    const int kof = ks * KHS;

    const int tid  = threadIdx.x;
    const int wid  = tid >> 5;
    const int lane = tid & 31;
    const uint32_t sb = s2u(smem);

    int*   s_tok = (int*)(smem + SM_TOK);
    float* s_wt  = (float*)(smem + SM_WT);
    {
        int m  = m0 + tid;
        int mm = (m < cnt) ? m : (cnt - 1);
        s_tok[tid] = g_tok[ex][mm];
        s_wt[tid]  = (m < cnt) ? g_wt[ex][m] : 0.f;
    }
    __syncthreads();

    // ---- cp.async chunk assignment (16B chunks, SW128 swizzled dst) ----
    const __half* aSrc[8]; uint32_t aDst[8];
#pragma unroll
    for (int i = 0; i < 8; i++) {
        int c = tid + i * NTHREADS, r = c >> 3, u = c & 7;
        const __half* rowp;
        if (FIRST) rowp = g_xh + (size_t)s_tok[r] * DDIM;
        else       rowp = g_H  + (size_t)(g_off[ex] + m0 + r) * FDIM;
        aSrc[i] = rowp + kof + u * 8;
        aDst[i] = sb + SM_A + r * 128 + ((u ^ (r & 7)) << 4);
    }
    const __half* bSrc[8]; uint32_t bDst[8];
    const __half* Wb = (FIRST ? g_W1h : g_W2h) + (size_t)ex * ((size_t)FDIM * DDIM);
#pragma unroll
    for (int i = 0; i < 8; i++) {
        int c = tid + i * NTHREADS, r = c >> 3, u = c & 7;
        bSrc[i] = Wb + (size_t)(n0 + r) * KH + kof + u * 8;
        bDst[i] = sb + SM_B + r * 128 + ((u ^ (r & 7)) << 4);
    }

    auto issue_stage = [&](int kt, int s) {
        const uint32_t off = (uint32_t)s * 16384u;
#pragma unroll
        for (int i = 0; i < 8; i++) CP_ASYNC16(aDst[i] + off, aSrc[i] + (size_t)kt * BKH);
#pragma unroll
        for (int i = 0; i < 8; i++) CP_ASYNC16(bDst[i] + off, bSrc[i] + (size_t)kt * BKH);
        CP_COMMIT();
    };

    // ---- warp / lane geometry (2x2 warps, 64x64 each) ----
    const int wm = wid >> 1;
    const int wn = wid & 1;
    const int laRow = lane & 15;
    const int laDu  = (lane >> 4) & 1;
    const int lbRow = (lane & 7) + ((lane & 16) >> 1);
    const int lbDu  = (lane >> 3) & 1;

    float acc[4][8][4];
#pragma unroll
    for (int i = 0; i < 4; i++)
#pragma unroll
        for (int j = 0; j < 8; j++)
#pragma unroll
            for (int r = 0; r < 4; r++) acc[i][j][r] = 0.f;

    const int NKT = KHS / BKH;

    issue_stage(0, 0);
    issue_stage(1, 1);

    for (int kt = 0; kt < NKT; kt++) {
        if (kt + 1 < NKT) { CP_WAIT(1); } else { CP_WAIT(0); }
        __syncthreads();
        // safe post-barrier prefetch: stage (kt+2)%3 was last read in iter kt-1
        if (kt + 2 < NKT) issue_stage(kt + 2, (kt + 2) % STAGES);

        const int s = kt % STAGES;
        const uint32_t As = sb + SM_A + s * 16384;
        const uint32_t Bs = sb + SM_B + s * 16384;

#pragma unroll
        for (int kk8 = 0; kk8 < 8; kk8 += 2) {   // 4 kk16 steps per K-tile
            uint32_t afr[4][4], bfr[8][2];
#pragma unroll
            for (int fm = 0; fm < 4; fm++) {
                int r = wm * 64 + fm * 16 + laRow;
                int u = kk8 + laDu;
                ldsm4(afr[fm], As + r * 128 + ((u ^ (r & 7)) << 4));
            }
#pragma unroll
            for (int fp = 0; fp < 4; fp++) {
                int r = wn * 64 + fp * 16 + lbRow;
                int u = kk8 + lbDu;
                uint32_t q[4];
                ldsm4(q, Bs + r * 128 + ((u ^ (r & 7)) << 4));
                bfr[2 * fp][0] = q[0]; bfr[2 * fp][1] = q[1];
                bfr[2 * fp + 1][0] = q[2]; bfr[2 * fp + 1][1] = q[3];
            }
#pragma unroll
            for (int fm = 0; fm < 4; fm++)
#pragma unroll
                for (int fn = 0; fn < 8; fn++)
                    mma_f16(acc[fm][fn], afr[fm], bfr[fn]);
        }
        // no trailing barrier: next iteration's top barrier fences reuse
    }

    // ---------------- epilogue ----------------
    const int er = lane >> 2;
    const int ec = (lane & 3) * 2;
    if (FIRST) {
        const int hb = g_off[ex];
#pragma unroll
        for (int fm = 0; fm < 4; fm++) {
#pragma unroll
            for (int hh = 0; hh < 2; hh++) {
                int mloc = wm * 64 + fm * 16 + er + hh * 8;
                int m = m0 + mloc;
                if (m < cnt) {
                    __half* dst = g_H + (size_t)(hb + m) * FDIM + n0 + wn * 64 + ec;
#pragma unroll
                    for (int fn = 0; fn < 8; fn++) {
                        float v0 = gelu_exact(acc[fm][fn][hh * 2 + 0]);
                        float v1 = gelu_exact(acc[fm][fn][hh * 2 + 1]);
                        *(__half2*)(dst + fn * 8) = __floats2half2_rn(v0, v1);
                    }
                }
            }
        }
    } else {
#pragma unroll
        for (int fm = 0; fm < 4; fm++) {
#pragma unroll
            for (int hh = 0; hh < 2; hh++) {
                int mloc = wm * 64 + fm * 16 + er + hh * 8;
                int m = m0 + mloc;
                if (m < cnt) {
                    int   tok = s_tok[mloc];
                    float w   = s_wt[mloc];
                    float* dst = OUT + (size_t)tok * DDIM + n0 + wn * 64 + ec;
#pragma unroll
                    for (int fn = 0; fn < 8; fn++) {
                        atomicAdd(dst + fn * 8 + 0, w * acc[fm][fn][hh * 2 + 0]);
                        atomicAdd(dst + fn * 8 + 1, w * acc[fm][fn][hh * 2 + 1]);
                    }
                }
            }
        }
    }
}

// ---------------- launch ----------------
extern "C" void kernel_launch(void* const* d_in, const int* in_sizes, int n_in,
                              void* d_out, int out_size) {
    const float* x  = (const float*)d_in[0];
    const float* Wg = (const float*)d_in[1];
    const float* We = (const float*)d_in[2];
    const float* W1 = (const float*)d_in[3];
    const float* W2 = (const float*)d_in[4];
    float* out = (float*)d_out;

    // output layout: [out (N*D)] [group_logits (N*G)] [group_entropy (1)]
    float* out_logits = out + (size_t)NTOK * DDIM;
    float* out_ent    = out_logits + (size_t)NTOK * GNUM;

    static __half* xh_p  = nullptr;
    static __half* w1h_p = nullptr;
    static __half* w2h_p = nullptr;
    static cudaStream_t s1, s2;
    static cudaEvent_t eFork, eCvtX, eW1a, eCvt1, eCvt2, eG1a, eG2a;
    if (!xh_p) {
        cudaGetSymbolAddress((void**)&xh_p,  g_xh);
        cudaGetSymbolAddress((void**)&w1h_p, g_W1h);
        cudaGetSymbolAddress((void**)&w2h_p, g_W2h);
        cudaFuncSetAttribute((const void*)gemm_fp16<DDIM, 1, true>,
                             cudaFuncAttributeMaxDynamicSharedMemorySize, SM_TOTAL);
        cudaFuncSetAttribute((const void*)gemm_fp16<FDIM, 2, false>,
                             cudaFuncAttributeMaxDynamicSharedMemorySize, SM_TOTAL);
        cudaStreamCreateWithFlags(&s1, cudaStreamNonBlocking);
        cudaStreamCreateWithFlags(&s2, cudaStreamNonBlocking);
        cudaEventCreateWithFlags(&eFork, cudaEventDisableTiming);
        cudaEventCreateWithFlags(&eCvtX, cudaEventDisableTiming);
        cudaEventCreateWithFlags(&eW1a,  cudaEventDisableTiming);
        cudaEventCreateWithFlags(&eCvt1, cudaEventDisableTiming);
        cudaEventCreateWithFlags(&eCvt2, cudaEventDisableTiming);
        cudaEventCreateWithFlags(&eG1a,  cudaEventDisableTiming);
        cudaEventCreateWithFlags(&eG2a,  cudaEventDisableTiming);
    }

    const int halfW = NEXP * FDIM * DDIM / 2;   // elements in 8 experts of W1/W2

    // --- fork ---
    cudaMemsetAsync(d_out, 0, (size_t)out_size * sizeof(float), 0);
    zero_cnt_kernel<<<1, 32>>>();
    cudaEventRecord(eFork, 0);
    cudaStreamWaitEvent(s1, eFork, 0);
    cudaStreamWaitEvent(s2, eFork, 0);

    // s1: W1 in expert halves (G1a can start after the first half)
    cvt_kernel<<<2048, 256, 0, s1>>>(W1, w1h_p, halfW / 8);
    cudaEventRecord(eW1a, s1);
    cvt_kernel<<<2048, 256, 0, s1>>>(W1 + halfW, w1h_p + halfW, halfW / 8);
    cudaEventRecord(eCvt1, s1);

    // s2: x (tiny, G1a needs it) then W2
    cvt_kernel<<<512, 256, 0, s2>>>(x, xh_p, NTOK * DDIM / 8);
    cudaEventRecord(eCvtX, s2);
    cvt_kernel<<<2048, 256, 0, s2>>>(W2, w2h_p, NEXP * DDIM * FDIM / 8);
    cudaEventRecord(eCvt2, s2);

    // stream 0: routing (reads f32 x directly)
    routing_kernel<<<(NTOK * 32 + 255) / 256, 256>>>(x, Wg, We, out_logits, out_ent);
    scan_kernel<<<1, 32>>>();

    // --- G1a: needs routing (program order) + W1 first half + xh ---
    cudaStreamWaitEvent(0, eW1a, 0);
    cudaStreamWaitEvent(0, eCvtX, 0);
    dim3 g1(FDIM / BN, NTOK / BM, NEXP / 2);
    gemm_fp16<DDIM, 1, true><<<g1, NTHREADS, SM_TOTAL>>>(nullptr, 0);
    cudaEventRecord(eG1a, 0);

    // --- G1b: needs full W1 ---
    cudaStreamWaitEvent(0, eCvt1, 0);
    gemm_fp16<DDIM, 1, true><<<g1, NTHREADS, SM_TOTAL>>>(nullptr, 8);

    // --- s2: G2a (experts 0..7) after cvt W2 (program order) + G1a ---
    cudaStreamWaitEvent(s2, eG1a, 0);
    dim3 g2(DDIM / BN, NTOK / BM, (NEXP / 2) * 2);
    gemm_fp16<FDIM, 2, false><<<g2, NTHREADS, SM_TOTAL, s2>>>(out, 0);
    cudaEventRecord(eG2a, s2);

    // --- stream 0: G2b (experts 8..15) after G1b (program order) + cvt W2 ---
    cudaStreamWaitEvent(0, eCvt2, 0);
    gemm_fp16<FDIM, 2, false><<<g2, NTHREADS, SM_TOTAL>>>(out, 8);

    // final join
    cudaStreamWaitEvent(0, eG2a, 0);
}

// round 13
// speedup vs baseline: 1.3947x; 1.0054x over previous
#include <cuda_runtime.h>
#include <cuda_fp16.h>
#include <cstdint>
#include <math.h>

// ---------------- problem constants ----------------
#define NTOK 4096      // B*T
#define DDIM 1024      // D
#define GNUM 4
#define FDIM 4096      // F
#define NEXP 16        // G*E
#define HROWS 10240    // 8192 pairs + per-expert 128-padding

// ---------------- GEMM tiling ----------------
#define BM 128
#define BN 128
#define BKH 64         // halves per K-tile (128 bytes = SW128 row)
#define STAGES 3
#define NTHREADS 256   // 8 warps (2x4), warp tile 64x32 -> 2 CTAs/SM, 4 warps/SMSP

#define SM_TOK   0
#define SM_WT    512
#define SM_A     1024                      // STAGES x 16384
#define SM_B     (SM_A + STAGES * 16384)
#define SM_TOTAL (SM_B + STAGES * 16384)   // 99328 -> 2 CTAs/SM

// ---------------- device scratch ----------------
__device__ int    g_cnt[NEXP];
__device__ int    g_off[NEXP];
__device__ int    g_tok[NEXP][NTOK];
__device__ float  g_wt [NEXP][NTOK];
__device__ __half g_H  [(size_t)HROWS * FDIM];            // 80 MB
__device__ __half g_xh [(size_t)NTOK * DDIM];             // 8 MB
__device__ __half g_W1h[(size_t)NEXP * FDIM * DDIM];      // 128 MB
__device__ __half g_W2h[(size_t)NEXP * DDIM * FDIM];      // 128 MB

// ---------------- helpers ----------------
__device__ __forceinline__ uint32_t s2u(const void* p) {
    uint32_t a;
    asm("{ .reg .u64 t; cvta.to.shared.u64 t, %1; cvt.u32.u64 %0, t; }" : "=r"(a) : "l"(p));
    return a;
}
__device__ __forceinline__ float gelu_exact(float v) {
    return 0.5f * v * (1.0f + erff(v * 0.7071067811865476f));
}
__device__ __forceinline__ void mma_f16(float c[4], const uint32_t a[4], const uint32_t b[2]) {
    asm volatile(
        "mma.sync.aligned.m16n8k16.row.col.f32.f16.f16.f32 "
        "{%0,%1,%2,%3}, {%4,%5,%6,%7}, {%8,%9}, {%0,%1,%2,%3};\n"
        : "+f"(c[0]), "+f"(c[1]), "+f"(c[2]), "+f"(c[3])
        : "r"(a[0]), "r"(a[1]), "r"(a[2]), "r"(a[3]), "r"(b[0]), "r"(b[1]));
}
__device__ __forceinline__ void ldsm4(uint32_t r[4], uint32_t addr) {
    asm volatile("ldmatrix.sync.aligned.m8n8.x4.shared.b16 {%0,%1,%2,%3}, [%4];"
        : "=r"(r[0]), "=r"(r[1]), "=r"(r[2]), "=r"(r[3]) : "r"(addr));
}
#define CP_ASYNC16(dst, src) \
    asm volatile("cp.async.cg.shared.global [%0], [%1], 16;" :: "r"(dst), "l"(src) : "memory")
#define CP_COMMIT() asm volatile("cp.async.commit_group;" ::: "memory")
#define CP_WAIT(n)  asm volatile("cp.async.wait_group %0;" :: "n"(n) : "memory")

// ---------------- kernel: f32 -> f16 conversion (prepass) ----------------
__global__ void cvt_kernel(const float* __restrict__ src, __half* __restrict__ dst, int n8) {
    int i = blockIdx.x * blockDim.x + threadIdx.x;
    int stride = gridDim.x * blockDim.x;
    for (; i < n8; i += stride) {
        const float4* s = (const float4*)src + (size_t)i * 2;
        float4 a = s[0], b = s[1];
        __half2 h0 = __floats2half2_rn(a.x, a.y);
        __half2 h1 = __floats2half2_rn(a.z, a.w);
        __half2 h2 = __floats2half2_rn(b.x, b.y);
        __half2 h3 = __floats2half2_rn(b.z, b.w);
        uint4 u;
        u.x = *(uint32_t*)&h0; u.y = *(uint32_t*)&h1;
        u.z = *(uint32_t*)&h2; u.w = *(uint32_t*)&h3;
        *((uint4*)dst + i) = u;
    }
}

// ---------------- kernel 0: zero expert counters ----------------
__global__ void zero_cnt_kernel() {
    if (threadIdx.x < NEXP) g_cnt[threadIdx.x] = 0;
}

// ---------------- kernel 1: routing (one warp per token) ----------------
__global__ void routing_kernel(const float* __restrict__ x,
                               const float* __restrict__ Wg,
                               const float* __restrict__ We,
                               float* __restrict__ out_logits,
                               float* __restrict__ out_ent) {
    int warp = (blockIdx.x * blockDim.x + threadIdx.x) >> 5;
    int lane = threadIdx.x & 31;
    if (warp >= NTOK) return;

    const float* xr = x + (size_t)warp * DDIM;
    float acc[20];
#pragma unroll
    for (int j = 0; j < 20; j++) acc[j] = 0.f;

    for (int k = lane; k < DDIM; k += 32) {
        float xv = xr[k];
#pragma unroll
        for (int g = 0; g < GNUM; g++) acc[g] += xv * Wg[g * DDIM + k];
#pragma unroll
        for (int j = 0; j < NEXP; j++) acc[4 + j] += xv * We[j * DDIM + k];
    }
#pragma unroll
    for (int o = 16; o > 0; o >>= 1) {
#pragma unroll
        for (int j = 0; j < 20; j++) acc[j] += __shfl_xor_sync(0xFFFFFFFFu, acc[j], o);
    }

    if (lane == 0) {
        float gl[4] = {acc[0], acc[1], acc[2], acc[3]};
#pragma unroll
        for (int g = 0; g < 4; g++) out_logits[warp * 4 + g] = gl[g];

        float mx = fmaxf(fmaxf(gl[0], gl[1]), fmaxf(gl[2], gl[3]));
        float ex4[4], s = 0.f;
#pragma unroll
        for (int g = 0; g < 4; g++) { ex4[g] = expf(gl[g] - mx); s += ex4[g]; }
        float ls = logf(s);
        float ent = 0.f;
#pragma unroll
        for (int g = 0; g < 4; g++) {
            float p = ex4[g] / s;
            ent -= p * (gl[g] - mx - ls);
        }
        atomicAdd(out_ent, ent * (1.0f / NTOK));

        int g0 = 0;
#pragma unroll
        for (int g = 1; g < 4; g++) if (gl[g] > gl[g0]) g0 = g;
        int g1 = -1;
#pragma unroll
        for (int g = 0; g < 4; g++) {
            if (g == g0) continue;
            if (g1 < 0 || gl[g] > gl[g1]) g1 = g;
        }
        float w0 = 1.f / (1.f + expf(gl[g1] - gl[g0]));
        float w1 = 1.f - w0;

        int   gs[2] = {g0, g1};
        float ws[2] = {w0, w1};
#pragma unroll
        for (int i = 0; i < 2; i++) {
            int g = gs[i];
            int eb = 4 + g * 4;
            int e = 0;
#pragma unroll
            for (int e2 = 1; e2 < 4; e2++) if (acc[eb + e2] > acc[eb + e]) e = e2;
            int exid = g * 4 + e;
            int slot = atomicAdd(&g_cnt[exid], 1);
            g_tok[exid][slot] = warp;
            g_wt[exid][slot]  = ws[i];
        }
    }
}

// ---------------- kernel 2: 16-entry padded prefix scan ----------------
__global__ void scan_kernel() {
    if (threadIdx.x == 0) {
        int o = 0;
        for (int e = 0; e < NEXP; e++) {
            g_off[e] = o;
            o += (g_cnt[e] + 127) & ~127;
        }
    }
}

// ---------------- fp16 tensor-core GEMM ----------------
// C[m,n] = sum_k A[m,k]*B[n,k]  (both K-contiguous fp16 in gmem)
// FIRST=true : A = gathered x (fp16), B = W1h[ex], epilogue gelu -> g_H (fp16)
// FIRST=false: A = g_H rows,         B = W2h[ex], epilogue w * atomicAdd -> out (f32)
// 256 threads = 8 warps (2x4), warp tile 64x32, mma.m16n8k16, 2 CTAs/SM
template <int KH, int SPLITK, bool FIRST>
__global__ void __launch_bounds__(NTHREADS, 2)
gemm_fp16(float* __restrict__ OUT, int zbase) {
    extern __shared__ char smem[];
    const int ex  = zbase + (int)blockIdx.z / SPLITK;
    const int ks  = (int)blockIdx.z % SPLITK;
    const int cnt = g_cnt[ex];
    const int m0  = blockIdx.y * BM;
    if (m0 >= cnt) return;
    const int n0  = blockIdx.x * BN;
    const int KHS = KH / SPLITK;
    const int kof = ks * KHS;

    const int tid  = threadIdx.x;
    const int wid  = tid >> 5;
    const int lane = tid & 31;
    const uint32_t sb = s2u(smem);

    int*   s_tok = (int*)(smem + SM_TOK);
    float* s_wt  = (float*)(smem + SM_WT);
    if (tid < BM) {
        int m  = m0 + tid;
        int mm = (m < cnt) ? m : (cnt - 1);
        s_tok[tid] = g_tok[ex][mm];
        s_wt[tid]  = (m < cnt) ? g_wt[ex][m] : 0.f;
    }
    __syncthreads();

    // ---- cp.async chunk assignment (16B chunks, SW128 swizzled dst) ----
    // A tile: 128 rows x 8 units = 1024 chunks, 4/thread; B tile same.
    const __half* aSrc[4]; uint32_t aDst[4];
#pragma unroll
    for (int i = 0; i < 4; i++) {
        int c = tid + i * NTHREADS, r = c >> 3, u = c & 7;
        const __half* rowp;
        if (FIRST) rowp = g_xh + (size_t)s_tok[r] * DDIM;
        else       rowp = g_H  + (size_t)(g_off[ex] + m0 + r) * FDIM;
        aSrc[i] = rowp + kof + u * 8;
        aDst[i] = sb + SM_A + r * 128 + ((u ^ (r & 7)) << 4);
    }
    const __half* bSrc[4]; uint32_t bDst[4];
    const __half* Wb = (FIRST ? g_W1h : g_W2h) + (size_t)ex * ((size_t)FDIM * DDIM);
#pragma unroll
    for (int i = 0; i < 4; i++) {
        int c = tid + i * NTHREADS, r = c >> 3, u = c & 7;
        bSrc[i] = Wb + (size_t)(n0 + r) * KH + kof + u * 8;
        bDst[i] = sb + SM_B + r * 128 + ((u ^ (r & 7)) << 4);
    }

    auto issue_stage = [&](int kt, int s) {
        const uint32_t off = (uint32_t)s * 16384u;
#pragma unroll
        for (int i = 0; i < 4; i++) CP_ASYNC16(aDst[i] + off, aSrc[i] + (size_t)kt * BKH);
#pragma unroll
        for (int i = 0; i < 4; i++) CP_ASYNC16(bDst[i] + off, bSrc[i] + (size_t)kt * BKH);
        CP_COMMIT();
    };

    // ---- warp / lane geometry (2x4 warps, 64x32 each) ----
    const int wm = wid >> 2;                 // 0..1: 64-row block
    const int wn = wid & 3;                  // 0..3: 32-col block
    const int laRow = lane & 15;
    const int laDu  = (lane >> 4) & 1;
    const int lbRow = (lane & 7) + ((lane & 16) >> 1);
    const int lbDu  = (lane >> 3) & 1;

    float acc[4][4][4];
#pragma unroll
    for (int i = 0; i < 4; i++)
#pragma unroll
        for (int j = 0; j < 4; j++)
#pragma unroll
            for (int r = 0; r < 4; r++) acc[i][j][r] = 0.f;

    const int NKT = KHS / BKH;

    issue_stage(0, 0);
    issue_stage(1, 1);

    for (int kt = 0; kt < NKT; kt++) {
        if (kt + 1 < NKT) { CP_WAIT(1); } else { CP_WAIT(0); }
        __syncthreads();
        // safe post-barrier prefetch: stage (kt+2)%3 was last read in iter kt-1
        if (kt + 2 < NKT) issue_stage(kt + 2, (kt + 2) % STAGES);

        const int s = kt % STAGES;
        const uint32_t As = sb + SM_A + s * 16384;
        const uint32_t Bs = sb + SM_B + s * 16384;

#pragma unroll
        for (int kk8 = 0; kk8 < 8; kk8 += 2) {   // 4 kk16 steps per K-tile
            uint32_t afr[4][4], bfr[4][2];
#pragma unroll
            for (int fm = 0; fm < 4; fm++) {
                int r = wm * 64 + fm * 16 + laRow;
                int u = kk8 + laDu;
                ldsm4(afr[fm], As + r * 128 + ((u ^ (r & 7)) << 4));
            }
#pragma unroll
            for (int fp = 0; fp < 2; fp++) {
                int r = wn * 32 + fp * 16 + lbRow;
                int u = kk8 + lbDu;
                uint32_t q[4];
                ldsm4(q, Bs + r * 128 + ((u ^ (r & 7)) << 4));
                bfr[2 * fp][0] = q[0]; bfr[2 * fp][1] = q[1];
                bfr[2 * fp + 1][0] = q[2]; bfr[2 * fp + 1][1] = q[3];
            }
#pragma unroll
            for (int fm = 0; fm < 4; fm++)
#pragma unroll
                for (int fn = 0; fn < 4; fn++)
                    mma_f16(acc[fm][fn], afr[fm], bfr[fn]);
        }
        // no trailing barrier: next iteration's top barrier fences reuse
    }

    // ---------------- epilogue ----------------
    const int er = lane >> 2;
    const int ec = (lane & 3) * 2;
    if (FIRST) {
        const int hb = g_off[ex];
#pragma unroll
        for (int fm = 0; fm < 4; fm++) {
#pragma unroll
            for (int hh = 0; hh < 2; hh++) {
                int mloc = wm * 64 + fm * 16 + er + hh * 8;
                int m = m0 + mloc;
                if (m < cnt) {
                    __half* dst = g_H + (size_t)(hb + m) * FDIM + n0 + wn * 32 + ec;
#pragma unroll
                    for (int fn = 0; fn < 4; fn++) {
                        float v0 = gelu_exact(acc[fm][fn][hh * 2 + 0]);
                        float v1 = gelu_exact(acc[fm][fn][hh * 2 + 1]);
                        *(__half2*)(dst + fn * 8) = __floats2half2_rn(v0, v1);
                    }
                }
            }
        }
    } else {
#pragma unroll
        for (int fm = 0; fm < 4; fm++) {
#pragma unroll
            for (int hh = 0; hh < 2; hh++) {
                int mloc = wm * 64 + fm * 16 + er + hh * 8;
                int m = m0 + mloc;
                if (m < cnt) {
                    int   tok = s_tok[mloc];
                    float w   = s_wt[mloc];
                    float* dst = OUT + (size_t)tok * DDIM + n0 + wn * 32 + ec;
#pragma unroll
                    for (int fn = 0; fn < 4; fn++) {
                        atomicAdd(dst + fn * 8 + 0, w * acc[fm][fn][hh * 2 + 0]);
                        atomicAdd(dst + fn * 8 + 1, w * acc[fm][fn][hh * 2 + 1]);
                    }
                }
            }
        }
    }
}

// ---------------- launch ----------------
extern "C" void kernel_launch(void* const* d_in, const int* in_sizes, int n_in,
                              void* d_out, int out_size) {
    const float* x  = (const float*)d_in[0];
    const float* Wg = (const float*)d_in[1];
    const float* We = (const float*)d_in[2];
    const float* W1 = (const float*)d_in[3];
    const float* W2 = (const float*)d_in[4];
    float* out = (float*)d_out;

    // output layout: [out (N*D)] [group_logits (N*G)] [group_entropy (1)]
    float* out_logits = out + (size_t)NTOK * DDIM;
    float* out_ent    = out_logits + (size_t)NTOK * GNUM;

    static __half* xh_p  = nullptr;
    static __half* w1h_p = nullptr;
    static __half* w2h_p = nullptr;
    static cudaStream_t s1, s2;
    static cudaEvent_t eFork, eCvtX, eW1a, eCvt1, eCvt2, eG1a, eG2a;
    if (!xh_p) {
        cudaGetSymbolAddress((void**)&xh_p,  g_xh);
        cudaGetSymbolAddress((void**)&w1h_p, g_W1h);
        cudaGetSymbolAddress((void**)&w2h_p, g_W2h);
        cudaFuncSetAttribute((const void*)gemm_fp16<DDIM, 1, true>,
                             cudaFuncAttributeMaxDynamicSharedMemorySize, SM_TOTAL);
        cudaFuncSetAttribute((const void*)gemm_fp16<FDIM, 2, false>,
                             cudaFuncAttributeMaxDynamicSharedMemorySize, SM_TOTAL);
        cudaStreamCreateWithFlags(&s1, cudaStreamNonBlocking);
        cudaStreamCreateWithFlags(&s2, cudaStreamNonBlocking);
        cudaEventCreateWithFlags(&eFork, cudaEventDisableTiming);
        cudaEventCreateWithFlags(&eCvtX, cudaEventDisableTiming);
        cudaEventCreateWithFlags(&eW1a,  cudaEventDisableTiming);
        cudaEventCreateWithFlags(&eCvt1, cudaEventDisableTiming);
        cudaEventCreateWithFlags(&eCvt2, cudaEventDisableTiming);
        cudaEventCreateWithFlags(&eG1a,  cudaEventDisableTiming);
        cudaEventCreateWithFlags(&eG2a,  cudaEventDisableTiming);
    }

    const int halfW = NEXP * FDIM * DDIM / 2;   // elements in 8 experts of W1/W2

    // --- fork ---
    cudaMemsetAsync(d_out, 0, (size_t)out_size * sizeof(float), 0);
    zero_cnt_kernel<<<1, 32>>>();
    cudaEventRecord(eFork, 0);
    cudaStreamWaitEvent(s1, eFork, 0);
    cudaStreamWaitEvent(s2, eFork, 0);

    // s1: W1 in expert halves (G1a can start after the first half)
    cvt_kernel<<<2048, 256, 0, s1>>>(W1, w1h_p, halfW / 8);
    cudaEventRecord(eW1a, s1);
    cvt_kernel<<<2048, 256, 0, s1>>>(W1 + halfW, w1h_p + halfW, halfW / 8);
    cudaEventRecord(eCvt1, s1);

    // s2: x (tiny, G1a needs it) then W2
    cvt_kernel<<<512, 256, 0, s2>>>(x, xh_p, NTOK * DDIM / 8);
    cudaEventRecord(eCvtX, s2);
    cvt_kernel<<<2048, 256, 0, s2>>>(W2, w2h_p, NEXP * DDIM * FDIM / 8);
    cudaEventRecord(eCvt2, s2);

    // stream 0: routing (reads f32 x directly)
    routing_kernel<<<(NTOK * 32 + 255) / 256, 256>>>(x, Wg, We, out_logits, out_ent);
    scan_kernel<<<1, 32>>>();

    // --- G1a: needs routing (program order) + W1 first half + xh ---
    cudaStreamWaitEvent(0, eW1a, 0);
    cudaStreamWaitEvent(0, eCvtX, 0);
    dim3 g1(FDIM / BN, NTOK / BM, NEXP / 2);
    gemm_fp16<DDIM, 1, true><<<g1, NTHREADS, SM_TOTAL>>>(nullptr, 0);
    cudaEventRecord(eG1a, 0);

    // --- G1b: needs full W1 ---
    cudaStreamWaitEvent(0, eCvt1, 0);
    gemm_fp16<DDIM, 1, true><<<g1, NTHREADS, SM_TOTAL>>>(nullptr, 8);

    // --- s2: G2a (experts 0..7) after cvt W2 (program order) + G1a ---
    cudaStreamWaitEvent(s2, eG1a, 0);
    dim3 g2(DDIM / BN, NTOK / BM, (NEXP / 2) * 2);
    gemm_fp16<FDIM, 2, false><<<g2, NTHREADS, SM_TOTAL, s2>>>(out, 0);
    cudaEventRecord(eG2a, s2);

    // --- stream 0: G2b (experts 8..15) after G1b (program order) + cvt W2 ---
    cudaStreamWaitEvent(0, eCvt2, 0);
    gemm_fp16<FDIM, 2, false><<<g2, NTHREADS, SM_TOTAL>>>(out, 8);

    // final join
    cudaStreamWaitEvent(0, eG2a, 0);
}

// round 14
// speedup vs baseline: 1.4267x; 1.0229x over previous
#include <cuda_runtime.h>
#include <cuda_fp16.h>
#include <cstdint>
#include <math.h>

// ---------------- problem constants ----------------
#define NTOK 4096      // B*T
#define DDIM 1024      // D
#define GNUM 4
#define FDIM 4096      // F
#define NEXP 16        // G*E
#define HROWS 10240    // 8192 pairs + per-expert 128-padding

// ---------------- GEMM tiling ----------------
#define BM 128
#define BN 128
#define BKH 64         // halves per K-tile (128 bytes = SW128 row)
#define STAGES 3
#define NTHREADS 256   // 8 warps (2x4), warp tile 64x32 -> 2 CTAs/SM
#define MTILES 10      // M-tiles per expert: supports cnt <= 1280 (>30 sigma of ~Bin(8192,1/16))

#define SM_TOK   0
#define SM_WT    512
#define SM_A     1024                      // STAGES x 16384
#define SM_B     (SM_A + STAGES * 16384)
#define SM_TOTAL (SM_B + STAGES * 16384)   // 99328 -> 2 CTAs/SM

// ---------------- device scratch ----------------
__device__ int    g_cnt[NEXP];
__device__ int    g_off[NEXP];
__device__ int    g_tok[NEXP][NTOK];
__device__ float  g_wt [NEXP][NTOK];
__device__ __half g_H  [(size_t)HROWS * FDIM];            // 80 MB
__device__ __half g_xh [(size_t)NTOK * DDIM];             // 8 MB
__device__ __half g_W1h[(size_t)NEXP * FDIM * DDIM];      // 128 MB
__device__ __half g_W2h[(size_t)NEXP * DDIM * FDIM];      // 128 MB

// ---------------- helpers ----------------
__device__ __forceinline__ uint32_t s2u(const void* p) {
    uint32_t a;
    asm("{ .reg .u64 t; cvta.to.shared.u64 t, %1; cvt.u32.u64 %0, t; }" : "=r"(a) : "l"(p));
    return a;
}
__device__ __forceinline__ float gelu_exact(float v) {
    return 0.5f * v * (1.0f + erff(v * 0.7071067811865476f));
}
__device__ __forceinline__ void mma_f16(float c[4], const uint32_t a[4], const uint32_t b[2]) {
    asm volatile(
        "mma.sync.aligned.m16n8k16.row.col.f32.f16.f16.f32 "
        "{%0,%1,%2,%3}, {%4,%5,%6,%7}, {%8,%9}, {%0,%1,%2,%3};\n"
        : "+f"(c[0]), "+f"(c[1]), "+f"(c[2]), "+f"(c[3])
        : "r"(a[0]), "r"(a[1]), "r"(a[2]), "r"(a[3]), "r"(b[0]), "r"(b[1]));
}
__device__ __forceinline__ void ldsm4(uint32_t r[4], uint32_t addr) {
    asm volatile("ldmatrix.sync.aligned.m8n8.x4.shared.b16 {%0,%1,%2,%3}, [%4];"
        : "=r"(r[0]), "=r"(r[1]), "=r"(r[2]), "=r"(r[3]) : "r"(addr));
}
#define CP_ASYNC16(dst, src) \
    asm volatile("cp.async.cg.shared.global [%0], [%1], 16;" :: "r"(dst), "l"(src) : "memory")
#define CP_COMMIT() asm volatile("cp.async.commit_group;" ::: "memory")
#define CP_WAIT(n)  asm volatile("cp.async.wait_group %0;" :: "n"(n) : "memory")

// ---------------- kernel: f32 -> f16 conversion (prepass) ----------------
__global__ void cvt_kernel(const float* __restrict__ src, __half* __restrict__ dst, int n8) {
    int i = blockIdx.x * blockDim.x + threadIdx.x;
    int stride = gridDim.x * blockDim.x;
    for (; i < n8; i += stride) {
        const float4* s = (const float4*)src + (size_t)i * 2;
        float4 a = s[0], b = s[1];
        __half2 h0 = __floats2half2_rn(a.x, a.y);
        __half2 h1 = __floats2half2_rn(a.z, a.w);
        __half2 h2 = __floats2half2_rn(b.x, b.y);
        __half2 h3 = __floats2half2_rn(b.z, b.w);
        uint4 u;
        u.x = *(uint32_t*)&h0; u.y = *(uint32_t*)&h1;
        u.z = *(uint32_t*)&h2; u.w = *(uint32_t*)&h3;
        *((uint4*)dst + i) = u;
    }
}

// ---------------- kernel 0: zero expert counters + entropy slot ------------
__global__ void zero_cnt_kernel(float* __restrict__ ent) {
    if (threadIdx.x < NEXP) g_cnt[threadIdx.x] = 0;
    if (threadIdx.x == 0) *ent = 0.f;
}

// ---------------- kernel 1: routing (one warp per token) ----------------
__global__ void routing_kernel(const float* __restrict__ x,
                               const float* __restrict__ Wg,
                               const float* __restrict__ We,
                               float* __restrict__ out_logits,
                               float* __restrict__ out_ent) {
    int warp = (blockIdx.x * blockDim.x + threadIdx.x) >> 5;
    int lane = threadIdx.x & 31;
    if (warp >= NTOK) return;

    const float* xr = x + (size_t)warp * DDIM;
    float acc[20];
#pragma unroll
    for (int j = 0; j < 20; j++) acc[j] = 0.f;

    for (int k = lane; k < DDIM; k += 32) {
        float xv = xr[k];
#pragma unroll
        for (int g = 0; g < GNUM; g++) acc[g] += xv * Wg[g * DDIM + k];
#pragma unroll
        for (int j = 0; j < NEXP; j++) acc[4 + j] += xv * We[j * DDIM + k];
    }
#pragma unroll
    for (int o = 16; o > 0; o >>= 1) {
#pragma unroll
        for (int j = 0; j < 20; j++) acc[j] += __shfl_xor_sync(0xFFFFFFFFu, acc[j], o);
    }

    if (lane == 0) {
        float gl[4] = {acc[0], acc[1], acc[2], acc[3]};
#pragma unroll
        for (int g = 0; g < 4; g++) out_logits[warp * 4 + g] = gl[g];

        float mx = fmaxf(fmaxf(gl[0], gl[1]), fmaxf(gl[2], gl[3]));
        float ex4[4], s = 0.f;
#pragma unroll
        for (int g = 0; g < 4; g++) { ex4[g] = expf(gl[g] - mx); s += ex4[g]; }
        float ls = logf(s);
        float ent = 0.f;
#pragma unroll
        for (int g = 0; g < 4; g++) {
            float p = ex4[g] / s;
            ent -= p * (gl[g] - mx - ls);
        }
        atomicAdd(out_ent, ent * (1.0f / NTOK));

        int g0 = 0;
#pragma unroll
        for (int g = 1; g < 4; g++) if (gl[g] > gl[g0]) g0 = g;
        int g1 = -1;
#pragma unroll
        for (int g = 0; g < 4; g++) {
            if (g == g0) continue;
            if (g1 < 0 || gl[g] > gl[g1]) g1 = g;
        }
        float w0 = 1.f / (1.f + expf(gl[g1] - gl[g0]));
        float w1 = 1.f - w0;

        int   gs[2] = {g0, g1};
        float ws[2] = {w0, w1};
#pragma unroll
        for (int i = 0; i < 2; i++) {
            int g = gs[i];
            int eb = 4 + g * 4;
            int e = 0;
#pragma unroll
            for (int e2 = 1; e2 < 4; e2++) if (acc[eb + e2] > acc[eb + e]) e = e2;
            int exid = g * 4 + e;
            int slot = atomicAdd(&g_cnt[exid], 1);
            g_tok[exid][slot] = warp;
            g_wt[exid][slot]  = ws[i];
        }
    }
}

// ---------------- kernel 2: 16-entry padded prefix scan ----------------
__global__ void scan_kernel() {
    if (threadIdx.x == 0) {
        int o = 0;
        for (int e = 0; e < NEXP; e++) {
            g_off[e] = o;
            o += (g_cnt[e] + 127) & ~127;
        }
    }
}

// ---------------- fp16 tensor-core GEMM ----------------
// C[m,n] = sum_k A[m,k]*B[n,k]  (both K-contiguous fp16 in gmem)
// FIRST=true : A = gathered x (fp16), B = W1h[ex], epilogue gelu -> g_H (fp16)
// FIRST=false: A = g_H rows,         B = W2h[ex], epilogue w * atomicAdd -> out (f32)
// 256 threads = 8 warps (2x4), warp tile 64x32, mma.m16n8k16, 2 CTAs/SM
template <int KH, int SPLITK, bool FIRST>
__global__ void __launch_bounds__(NTHREADS, 2)
gemm_fp16(float* __restrict__ OUT, int zbase) {
    extern __shared__ char smem[];
    const int ex  = zbase + (int)blockIdx.z / SPLITK;
    const int ks  = (int)blockIdx.z % SPLITK;
    const int cnt = g_cnt[ex];
    const int m0  = blockIdx.y * BM;
    if (m0 >= cnt) return;
    const int n0  = blockIdx.x * BN;
    const int KHS = KH / SPLITK;
    const int kof = ks * KHS;

    const int tid  = threadIdx.x;
    const int wid  = tid >> 5;
    const int lane = tid & 31;
    const uint32_t sb = s2u(smem);

    int*   s_tok = (int*)(smem + SM_TOK);
    float* s_wt  = (float*)(smem + SM_WT);
    if (tid < BM) {
        int m  = m0 + tid;
        int mm = (m < cnt) ? m : (cnt - 1);
        s_tok[tid] = g_tok[ex][mm];
        s_wt[tid]  = (m < cnt) ? g_wt[ex][m] : 0.f;
    }
    __syncthreads();

    // ---- cp.async chunk assignment (16B chunks, SW128 swizzled dst) ----
    const __half* aSrc[4]; uint32_t aDst[4];
#pragma unroll
    for (int i = 0; i < 4; i++) {
        int c = tid + i * NTHREADS, r = c >> 3, u = c & 7;
        const __half* rowp;
        if (FIRST) rowp = g_xh + (size_t)s_tok[r] * DDIM;
        else       rowp = g_H  + (size_t)(g_off[ex] + m0 + r) * FDIM;
        aSrc[i] = rowp + kof + u * 8;
        aDst[i] = sb + SM_A + r * 128 + ((u ^ (r & 7)) << 4);
    }
    const __half* bSrc[4]; uint32_t bDst[4];
    const __half* Wb = (FIRST ? g_W1h : g_W2h) + (size_t)ex * ((size_t)FDIM * DDIM);
#pragma unroll
    for (int i = 0; i < 4; i++) {
        int c = tid + i * NTHREADS, r = c >> 3, u = c & 7;
        bSrc[i] = Wb + (size_t)(n0 + r) * KH + kof + u * 8;
        bDst[i] = sb + SM_B + r * 128 + ((u ^ (r & 7)) << 4);
    }

    auto issue_stage = [&](int kt, int s) {
        const uint32_t off = (uint32_t)s * 16384u;
#pragma unroll
        for (int i = 0; i < 4; i++) CP_ASYNC16(aDst[i] + off, aSrc[i] + (size_t)kt * BKH);
#pragma unroll
        for (int i = 0; i < 4; i++) CP_ASYNC16(bDst[i] + off, bSrc[i] + (size_t)kt * BKH);
        CP_COMMIT();
    };

    // ---- warp / lane geometry (2x4 warps, 64x32 each) ----
    const int wm = wid >> 2;                 // 0..1: 64-row block
    const int wn = wid & 3;                  // 0..3: 32-col block
    const int laRow = lane & 15;
    const int laDu  = (lane >> 4) & 1;
    const int lbRow = (lane & 7) + ((lane & 16) >> 1);
    const int lbDu  = (lane >> 3) & 1;

    float acc[4][4][4];
#pragma unroll
    for (int i = 0; i < 4; i++)
#pragma unroll
        for (int j = 0; j < 4; j++)
#pragma unroll
            for (int r = 0; r < 4; r++) acc[i][j][r] = 0.f;

    const int NKT = KHS / BKH;

    issue_stage(0, 0);
    issue_stage(1, 1);

    for (int kt = 0; kt < NKT; kt++) {
        if (kt + 1 < NKT) { CP_WAIT(1); } else { CP_WAIT(0); }
        __syncthreads();
        // safe post-barrier prefetch: stage (kt+2)%3 was last read in iter kt-1
        if (kt + 2 < NKT) issue_stage(kt + 2, (kt + 2) % STAGES);

        const int s = kt % STAGES;
        const uint32_t As = sb + SM_A + s * 16384;
        const uint32_t Bs = sb + SM_B + s * 16384;

#pragma unroll
        for (int kk8 = 0; kk8 < 8; kk8 += 2) {   // 4 kk16 steps per K-tile
            uint32_t afr[4][4], bfr[4][2];
#pragma unroll
            for (int fm = 0; fm < 4; fm++) {
                int r = wm * 64 + fm * 16 + laRow;
                int u = kk8 + laDu;
                ldsm4(afr[fm], As + r * 128 + ((u ^ (r & 7)) << 4));
            }
#pragma unroll
            for (int fp = 0; fp < 2; fp++) {
                int r = wn * 32 + fp * 16 + lbRow;
                int u = kk8 + lbDu;
                uint32_t q[4];
                ldsm4(q, Bs + r * 128 + ((u ^ (r & 7)) << 4));
                bfr[2 * fp][0] = q[0]; bfr[2 * fp][1] = q[1];
                bfr[2 * fp + 1][0] = q[2]; bfr[2 * fp + 1][1] = q[3];
            }
#pragma unroll
            for (int fm = 0; fm < 4; fm++)
#pragma unroll
                for (int fn = 0; fn < 4; fn++)
                    mma_f16(acc[fm][fn], afr[fm], bfr[fn]);
        }
        // no trailing barrier: next iteration's top barrier fences reuse
    }

    // ---------------- epilogue ----------------
    const int er = lane >> 2;
    const int ec = (lane & 3) * 2;
    if (FIRST) {
        const int hb = g_off[ex];
#pragma unroll
        for (int fm = 0; fm < 4; fm++) {
#pragma unroll
            for (int hh = 0; hh < 2; hh++) {
                int mloc = wm * 64 + fm * 16 + er + hh * 8;
                int m = m0 + mloc;
                if (m < cnt) {
                    __half* dst = g_H + (size_t)(hb + m) * FDIM + n0 + wn * 32 + ec;
#pragma unroll
                    for (int fn = 0; fn < 4; fn++) {
                        float v0 = gelu_exact(acc[fm][fn][hh * 2 + 0]);
                        float v1 = gelu_exact(acc[fm][fn][hh * 2 + 1]);
                        *(__half2*)(dst + fn * 8) = __floats2half2_rn(v0, v1);
                    }
                }
            }
        }
    } else {
#pragma unroll
        for (int fm = 0; fm < 4; fm++) {
#pragma unroll
            for (int hh = 0; hh < 2; hh++) {
                int mloc = wm * 64 + fm * 16 + er + hh * 8;
                int m = m0 + mloc;
                if (m < cnt) {
                    int   tok = s_tok[mloc];
                    float w   = s_wt[mloc];
                    float* dst = OUT + (size_t)tok * DDIM + n0 + wn * 32 + ec;
#pragma unroll
                    for (int fn = 0; fn < 4; fn++) {
                        atomicAdd(dst + fn * 8 + 0, w * acc[fm][fn][hh * 2 + 0]);
                        atomicAdd(dst + fn * 8 + 1, w * acc[fm][fn][hh * 2 + 1]);
                    }
                }
            }
        }
    }
}

// ---------------- launch ----------------
extern "C" void kernel_launch(void* const* d_in, const int* in_sizes, int n_in,
                              void* d_out, int out_size) {
    const float* x  = (const float*)d_in[0];
    const float* Wg = (const float*)d_in[1];
    const float* We = (const float*)d_in[2];
    const float* W1 = (const float*)d_in[3];
    const float* W2 = (const float*)d_in[4];
    float* out = (float*)d_out;

    // output layout: [out (N*D)] [group_logits (N*G)] [group_entropy (1)]
    float* out_logits = out + (size_t)NTOK * DDIM;
    float* out_ent    = out_logits + (size_t)NTOK * GNUM;

    static __half* xh_p  = nullptr;
    static __half* w1h_p = nullptr;
    static __half* w2h_p = nullptr;
    static cudaStream_t s1, s2;
    static cudaEvent_t eFork, eCvtX, eW1a, eCvt1, eCvt2, eG1a, eG2a;
    if (!xh_p) {
        cudaGetSymbolAddress((void**)&xh_p,  g_xh);
        cudaGetSymbolAddress((void**)&w1h_p, g_W1h);
        cudaGetSymbolAddress((void**)&w2h_p, g_W2h);
        cudaFuncSetAttribute((const void*)gemm_fp16<DDIM, 1, true>,
                             cudaFuncAttributeMaxDynamicSharedMemorySize, SM_TOTAL);
        cudaFuncSetAttribute((const void*)gemm_fp16<FDIM, 2, false>,
                             cudaFuncAttributeMaxDynamicSharedMemorySize, SM_TOTAL);
        cudaStreamCreateWithFlags(&s1, cudaStreamNonBlocking);
        cudaStreamCreateWithFlags(&s2, cudaStreamNonBlocking);
        cudaEventCreateWithFlags(&eFork, cudaEventDisableTiming);
        cudaEventCreateWithFlags(&eCvtX, cudaEventDisableTiming);
        cudaEventCreateWithFlags(&eW1a,  cudaEventDisableTiming);
        cudaEventCreateWithFlags(&eCvt1, cudaEventDisableTiming);
        cudaEventCreateWithFlags(&eCvt2, cudaEventDisableTiming);
        cudaEventCreateWithFlags(&eG1a,  cudaEventDisableTiming);
        cudaEventCreateWithFlags(&eG2a,  cudaEventDisableTiming);
    }

    const int halfW = NEXP * FDIM * DDIM / 2;   // elements in 8 experts of W1/W2

    // --- fork immediately (no big memset on the critical stream) ---
    zero_cnt_kernel<<<1, 32>>>(out_ent);
    cudaEventRecord(eFork, 0);
    cudaStreamWaitEvent(s1, eFork, 0);
    cudaStreamWaitEvent(s2, eFork, 0);

    // s1: W1 in expert halves (G1a can start after the first half)
    cvt_kernel<<<2048, 256, 0, s1>>>(W1, w1h_p, halfW / 8);
    cudaEventRecord(eW1a, s1);
    cvt_kernel<<<2048, 256, 0, s1>>>(W1 + halfW, w1h_p + halfW, halfW / 8);
    cudaEventRecord(eCvt1, s1);

    // s2: x (tiny, G1a needs it) -> out memset (G2 needs it) -> W2
    cvt_kernel<<<512, 256, 0, s2>>>(x, xh_p, NTOK * DDIM / 8);
    cudaEventRecord(eCvtX, s2);
    cudaMemsetAsync(out, 0, (size_t)NTOK * DDIM * sizeof(float), s2);
    cvt_kernel<<<2048, 256, 0, s2>>>(W2, w2h_p, NEXP * DDIM * FDIM / 8);
    cudaEventRecord(eCvt2, s2);

    // stream 0: routing (reads f32 x directly; writes logits + entropy)
    routing_kernel<<<(NTOK * 32 + 255) / 256, 256>>>(x, Wg, We, out_logits, out_ent);
    scan_kernel<<<1, 32>>>();

    // --- G1a: needs routing (program order) + W1 first half + xh ---
    cudaStreamWaitEvent(0, eW1a, 0);
    cudaStreamWaitEvent(0, eCvtX, 0);
    dim3 g1(FDIM / BN, MTILES, NEXP / 2);
    gemm_fp16<DDIM, 1, true><<<g1, NTHREADS, SM_TOTAL>>>(nullptr, 0);
    cudaEventRecord(eG1a, 0);

    // --- G1b: needs full W1 ---
    cudaStreamWaitEvent(0, eCvt1, 0);
    gemm_fp16<DDIM, 1, true><<<g1, NTHREADS, SM_TOTAL>>>(nullptr, 8);

    // --- s2: G2a (experts 0..7) after memset+cvt W2 (program order) + G1a ---
    cudaStreamWaitEvent(s2, eG1a, 0);
    dim3 g2(DDIM / BN, MTILES, (NEXP / 2) * 2);
    gemm_fp16<FDIM, 2, false><<<g2, NTHREADS, SM_TOTAL, s2>>>(out, 0);
    cudaEventRecord(eG2a, s2);

    // --- stream 0: G2b (experts 8..15) after G1b (program order) + cvt W2/memset ---
    cudaStreamWaitEvent(0, eCvt2, 0);
    gemm_fp16<FDIM, 2, false><<<g2, NTHREADS, SM_TOTAL>>>(out, 8);

    // final join
    cudaStreamWaitEvent(0, eG2a, 0);
}

// round 16
// speedup vs baseline: 1.4514x; 1.0173x over previous
#include <cuda_runtime.h>
#include <cuda_fp16.h>
#include <cstdint>
#include <math.h>

// ---------------- problem constants ----------------
#define NTOK 4096      // B*T
#define DDIM 1024      // D
#define GNUM 4
#define FDIM 4096      // F
#define NEXP 16        // G*E
#define HROWS 10240    // 8192 pairs + per-expert 128-padding

// ---------------- GEMM tiling ----------------
#define BM 128
#define BN 128
#define BKH 64         // halves per K-tile (128 bytes = SW128 row)
#define STAGES 3
#define NTHREADS 256   // 8 warps (2x4), warp tile 64x32 -> 2 CTAs/SM
#define MTILES 10      // M-tiles per expert: supports cnt <= 1280 (>30 sigma of ~Bin(8192,1/16))

#define SM_TOK   0
#define SM_WT    512
#define SM_A     1024                      // STAGES x 16384
#define SM_B     (SM_A + STAGES * 16384)
#define SM_TOTAL (SM_B + STAGES * 16384)   // 99328 -> 2 CTAs/SM

// ---------------- device scratch ----------------
__device__ int    g_cnt[NEXP];
__device__ int    g_off[NEXP];
__device__ int    g_tok[NEXP][NTOK];
__device__ float  g_wt [NEXP][NTOK];
__device__ __half g_H  [(size_t)HROWS * FDIM];            // 80 MB
__device__ __half g_xh [(size_t)NTOK * DDIM];             // 8 MB
__device__ __half g_W1h[(size_t)NEXP * FDIM * DDIM];      // 128 MB
__device__ __half g_W2h[(size_t)NEXP * DDIM * FDIM];      // 128 MB

// ---------------- helpers ----------------
__device__ __forceinline__ uint32_t s2u(const void* p) {
    uint32_t a;
    asm("{ .reg .u64 t; cvta.to.shared.u64 t, %1; cvt.u32.u64 %0, t; }" : "=r"(a) : "l"(p));
    return a;
}
__device__ __forceinline__ float gelu_exact(float v) {
    return 0.5f * v * (1.0f + erff(v * 0.7071067811865476f));
}
__device__ __forceinline__ void mma_f16(float c[4], const uint32_t a[4], const uint32_t b[2]) {
    asm volatile(
        "mma.sync.aligned.m16n8k16.row.col.f32.f16.f16.f32 "
        "{%0,%1,%2,%3}, {%4,%5,%6,%7}, {%8,%9}, {%0,%1,%2,%3};\n"
        : "+f"(c[0]), "+f"(c[1]), "+f"(c[2]), "+f"(c[3])
        : "r"(a[0]), "r"(a[1]), "r"(a[2]), "r"(a[3]), "r"(b[0]), "r"(b[1]));
}
__device__ __forceinline__ void ldsm4(uint32_t r[4], uint32_t addr) {
    asm volatile("ldmatrix.sync.aligned.m8n8.x4.shared.b16 {%0,%1,%2,%3}, [%4];"
        : "=r"(r[0]), "=r"(r[1]), "=r"(r[2]), "=r"(r[3]) : "r"(addr));
}
#define CP_ASYNC16(dst, src) \
    asm volatile("cp.async.cg.shared.global [%0], [%1], 16;" :: "r"(dst), "l"(src) : "memory")
#define CP_COMMIT() asm volatile("cp.async.commit_group;" ::: "memory")
#define CP_WAIT(n)  asm volatile("cp.async.wait_group %0;" :: "n"(n) : "memory")

// ---------------- kernel: f32 -> f16 conversion (prepass) ----------------
__global__ void cvt_kernel(const float* __restrict__ src, __half* __restrict__ dst, int n8) {
    int i = blockIdx.x * blockDim.x + threadIdx.x;
    int stride = gridDim.x * blockDim.x;
    for (; i < n8; i += stride) {
        const float4* s = (const float4*)src + (size_t)i * 2;
        float4 a = s[0], b = s[1];
        __half2 h0 = __floats2half2_rn(a.x, a.y);
        __half2 h1 = __floats2half2_rn(a.z, a.w);
        __half2 h2 = __floats2half2_rn(b.x, b.y);
        __half2 h3 = __floats2half2_rn(b.z, b.w);
        uint4 u;
        u.x = *(uint32_t*)&h0; u.y = *(uint32_t*)&h1;
        u.z = *(uint32_t*)&h2; u.w = *(uint32_t*)&h3;
        *((uint4*)dst + i) = u;
    }
}

// ---------------- kernel 0: zero expert counters + entropy slot ------------
__global__ void zero_cnt_kernel(float* __restrict__ ent) {
    if (threadIdx.x < NEXP) g_cnt[threadIdx.x] = 0;
    if (threadIdx.x == 0) *ent = 0.f;
}

// ---------------- kernel 1: routing (one warp per token) ----------------
__global__ void routing_kernel(const float* __restrict__ x,
                               const float* __restrict__ Wg,
                               const float* __restrict__ We,
                               float* __restrict__ out_logits,
                               float* __restrict__ out_ent) {
    int warp = (blockIdx.x * blockDim.x + threadIdx.x) >> 5;
    int lane = threadIdx.x & 31;
    if (warp >= NTOK) return;

    const float* xr = x + (size_t)warp * DDIM;
    float acc[20];
#pragma unroll
    for (int j = 0; j < 20; j++) acc[j] = 0.f;

    for (int k = lane; k < DDIM; k += 32) {
        float xv = xr[k];
#pragma unroll
        for (int g = 0; g < GNUM; g++) acc[g] += xv * Wg[g * DDIM + k];
#pragma unroll
        for (int j = 0; j < NEXP; j++) acc[4 + j] += xv * We[j * DDIM + k];
    }
#pragma unroll
    for (int o = 16; o > 0; o >>= 1) {
#pragma unroll
        for (int j = 0; j < 20; j++) acc[j] += __shfl_xor_sync(0xFFFFFFFFu, acc[j], o);
    }

    if (lane == 0) {
        float gl[4] = {acc[0], acc[1], acc[2], acc[3]};
#pragma unroll
        for (int g = 0; g < 4; g++) out_logits[warp * 4 + g] = gl[g];

        float mx = fmaxf(fmaxf(gl[0], gl[1]), fmaxf(gl[2], gl[3]));
        float ex4[4], s = 0.f;
#pragma unroll
        for (int g = 0; g < 4; g++) { ex4[g] = expf(gl[g] - mx); s += ex4[g]; }
        float ls = logf(s);
        float ent = 0.f;
#pragma unroll
        for (int g = 0; g < 4; g++) {
            float p = ex4[g] / s;
            ent -= p * (gl[g] - mx - ls);
        }
        atomicAdd(out_ent, ent * (1.0f / NTOK));

        int g0 = 0;
#pragma unroll
        for (int g = 1; g < 4; g++) if (gl[g] > gl[g0]) g0 = g;
        int g1 = -1;
#pragma unroll
        for (int g = 0; g < 4; g++) {
            if (g == g0) continue;
            if (g1 < 0 || gl[g] > gl[g1]) g1 = g;
        }
        float w0 = 1.f / (1.f + expf(gl[g1] - gl[g0]));
        float w1 = 1.f - w0;

        int   gs[2] = {g0, g1};
        float ws[2] = {w0, w1};
#pragma unroll
        for (int i = 0; i < 2; i++) {
            int g = gs[i];
            int eb = 4 + g * 4;
            int e = 0;
#pragma unroll
            for (int e2 = 1; e2 < 4; e2++) if (acc[eb + e2] > acc[eb + e]) e = e2;
            int exid = g * 4 + e;
            int slot = atomicAdd(&g_cnt[exid], 1);
            g_tok[exid][slot] = warp;
            g_wt[exid][slot]  = ws[i];
        }
    }
}

// ---------------- kernel 2: 16-entry padded prefix scan ----------------
__global__ void scan_kernel() {
    if (threadIdx.x == 0) {
        int o = 0;
        for (int e = 0; e < NEXP; e++) {
            g_off[e] = o;
            o += (g_cnt[e] + 127) & ~127;
        }
    }
}

// ---------------- fp16 tensor-core GEMM ----------------
// C[m,n] = sum_k A[m,k]*B[n,k]  (both K-contiguous fp16 in gmem)
// FIRST=true : A = gathered x (fp16), B = W1h[ex], epilogue gelu -> g_H (fp16)
// FIRST=false: A = g_H rows,         B = W2h[ex], epilogue w * atomicAdd -> out (f32)
// 256 threads = 8 warps (2x4), warp tile 64x32, mma.m16n8k16, 2 CTAs/SM
template <int KH, int SPLITK, bool FIRST>
__global__ void __launch_bounds__(NTHREADS, 2)
gemm_fp16(float* __restrict__ OUT, int zbase) {
    extern __shared__ char smem[];
    const int ex  = zbase + (int)blockIdx.z / SPLITK;
    const int ks  = (int)blockIdx.z % SPLITK;
    const int cnt = g_cnt[ex];
    const int m0  = blockIdx.y * BM;
    if (m0 >= cnt) return;
    const int n0  = blockIdx.x * BN;
    const int KHS = KH / SPLITK;
    const int kof = ks * KHS;

    const int tid  = threadIdx.x;
    const int wid  = tid >> 5;
    const int lane = tid & 31;
    const uint32_t sb = s2u(smem);

    int*   s_tok = (int*)(smem + SM_TOK);
    float* s_wt  = (float*)(smem + SM_WT);
    if (tid < BM) {
        int m  = m0 + tid;
        int mm = (m < cnt) ? m : (cnt - 1);
        s_tok[tid] = g_tok[ex][mm];
        s_wt[tid]  = (m < cnt) ? g_wt[ex][m] : 0.f;
    }
    __syncthreads();

    // ---- cp.async chunk assignment (16B chunks, SW128 swizzled dst) ----
    const __half* aSrc[4]; uint32_t aDst[4];
#pragma unroll
    for (int i = 0; i < 4; i++) {
        int c = tid + i * NTHREADS, r = c >> 3, u = c & 7;
        const __half* rowp;
        if (FIRST) rowp = g_xh + (size_t)s_tok[r] * DDIM;
        else       rowp = g_H  + (size_t)(g_off[ex] + m0 + r) * FDIM;
        aSrc[i] = rowp + kof + u * 8;
        aDst[i] = sb + SM_A + r * 128 + ((u ^ (r & 7)) << 4);
    }
    const __half* bSrc[4]; uint32_t bDst[4];
    const __half* Wb = (FIRST ? g_W1h : g_W2h) + (size_t)ex * ((size_t)FDIM * DDIM);
#pragma unroll
    for (int i = 0; i < 4; i++) {
        int c = tid + i * NTHREADS, r = c >> 3, u = c & 7;
        bSrc[i] = Wb + (size_t)(n0 + r) * KH + kof + u * 8;
        bDst[i] = sb + SM_B + r * 128 + ((u ^ (r & 7)) << 4);
    }

    auto issue_stage = [&](int kt, int s) {
        const uint32_t off = (uint32_t)s * 16384u;
#pragma unroll
        for (int i = 0; i < 4; i++) CP_ASYNC16(aDst[i] + off, aSrc[i] + (size_t)kt * BKH);
#pragma unroll
        for (int i = 0; i < 4; i++) CP_ASYNC16(bDst[i] + off, bSrc[i] + (size_t)kt * BKH);
        CP_COMMIT();
    };

    // ---- warp / lane geometry (2x4 warps, 64x32 each) ----
    const int wm = wid >> 2;                 // 0..1: 64-row block
    const int wn = wid & 3;                  // 0..3: 32-col block
    const int laRow = lane & 15;
    const int laDu  = (lane >> 4) & 1;
    const int lbRow = (lane & 7) + ((lane & 16) >> 1);
    const int lbDu  = (lane >> 3) & 1;

    float acc[4][4][4];
#pragma unroll
    for (int i = 0; i < 4; i++)
#pragma unroll
        for (int j = 0; j < 4; j++)
#pragma unroll
            for (int r = 0; r < 4; r++) acc[i][j][r] = 0.f;

    const int NKT = KHS / BKH;

    issue_stage(0, 0);
    issue_stage(1, 1);

    for (int kt = 0; kt < NKT; kt++) {
        if (kt + 1 < NKT) { CP_WAIT(1); } else { CP_WAIT(0); }
        __syncthreads();
        // safe post-barrier prefetch: stage (kt+2)%3 was last read in iter kt-1
        if (kt + 2 < NKT) issue_stage(kt + 2, (kt + 2) % STAGES);

        const int s = kt % STAGES;
        const uint32_t As = sb + SM_A + s * 16384;
        const uint32_t Bs = sb + SM_B + s * 16384;

#pragma unroll
        for (int kk8 = 0; kk8 < 8; kk8 += 2) {   // 4 kk16 steps per K-tile
            uint32_t afr[4][4], bfr[4][2];
#pragma unroll
            for (int fm = 0; fm < 4; fm++) {
                int r = wm * 64 + fm * 16 + laRow;
                int u = kk8 + laDu;
                ldsm4(afr[fm], As + r * 128 + ((u ^ (r & 7)) << 4));
            }
#pragma unroll
            for (int fp = 0; fp < 2; fp++) {
                int r = wn * 32 + fp * 16 + lbRow;
                int u = kk8 + lbDu;
                uint32_t q[4];
                ldsm4(q, Bs + r * 128 + ((u ^ (r & 7)) << 4));
                bfr[2 * fp][0] = q[0]; bfr[2 * fp][1] = q[1];
                bfr[2 * fp + 1][0] = q[2]; bfr[2 * fp + 1][1] = q[3];
            }
#pragma unroll
            for (int fm = 0; fm < 4; fm++)
#pragma unroll
                for (int fn = 0; fn < 4; fn++)
                    mma_f16(acc[fm][fn], afr[fm], bfr[fn]);
        }
        // no trailing barrier: next iteration's top barrier fences reuse
    }

    // ---------------- epilogue ----------------
    const int er = lane >> 2;
    const int ec = (lane & 3) * 2;
    if (FIRST) {
        const int hb = g_off[ex];
#pragma unroll
        for (int fm = 0; fm < 4; fm++) {
#pragma unroll
            for (int hh = 0; hh < 2; hh++) {
                int mloc = wm * 64 + fm * 16 + er + hh * 8;
                int m = m0 + mloc;
                if (m < cnt) {
                    __half* dst = g_H + (size_t)(hb + m) * FDIM + n0 + wn * 32 + ec;
#pragma unroll
                    for (int fn = 0; fn < 4; fn++) {
                        float v0 = gelu_exact(acc[fm][fn][hh * 2 + 0]);
                        float v1 = gelu_exact(acc[fm][fn][hh * 2 + 1]);
                        *(__half2*)(dst + fn * 8) = __floats2half2_rn(v0, v1);
                    }
                }
            }
        }
    } else {
#pragma unroll
        for (int fm = 0; fm < 4; fm++) {
#pragma unroll
            for (int hh = 0; hh < 2; hh++) {
                int mloc = wm * 64 + fm * 16 + er + hh * 8;
                int m = m0 + mloc;
                if (m < cnt) {
                    int   tok = s_tok[mloc];
                    float w   = s_wt[mloc];
                    float* dst = OUT + (size_t)tok * DDIM + n0 + wn * 32 + ec;
#pragma unroll
                    for (int fn = 0; fn < 4; fn++) {
                        atomicAdd(dst + fn * 8 + 0, w * acc[fm][fn][hh * 2 + 0]);
                        atomicAdd(dst + fn * 8 + 1, w * acc[fm][fn][hh * 2 + 1]);
                    }
                }
            }
        }
    }
}

// ---------------- launch ----------------
extern "C" void kernel_launch(void* const* d_in, const int* in_sizes, int n_in,
                              void* d_out, int out_size) {
    const float* x  = (const float*)d_in[0];
    const float* Wg = (const float*)d_in[1];
    const float* We = (const float*)d_in[2];
    const float* W1 = (const float*)d_in[3];
    const float* W2 = (const float*)d_in[4];
    float* out = (float*)d_out;

    // output layout: [out (N*D)] [group_logits (N*G)] [group_entropy (1)]
    float* out_logits = out + (size_t)NTOK * DDIM;
    float* out_ent    = out_logits + (size_t)NTOK * GNUM;

    static __half* xh_p  = nullptr;
    static __half* w1h_p = nullptr;
    static __half* w2h_p = nullptr;
    static cudaStream_t s1, s2;
    static cudaEvent_t eFork, eCvtX, eW1a, eScan, eG1a, eG1b, eCvt2, eG2a;
    if (!xh_p) {
        cudaGetSymbolAddress((void**)&xh_p,  g_xh);
        cudaGetSymbolAddress((void**)&w1h_p, g_W1h);
        cudaGetSymbolAddress((void**)&w2h_p, g_W2h);
        cudaFuncSetAttribute((const void*)gemm_fp16<DDIM, 1, true>,
                             cudaFuncAttributeMaxDynamicSharedMemorySize, SM_TOTAL);
        cudaFuncSetAttribute((const void*)gemm_fp16<FDIM, 2, false>,
                             cudaFuncAttributeMaxDynamicSharedMemorySize, SM_TOTAL);
        cudaStreamCreateWithFlags(&s1, cudaStreamNonBlocking);
        cudaStreamCreateWithFlags(&s2, cudaStreamNonBlocking);
        cudaEventCreateWithFlags(&eFork, cudaEventDisableTiming);
        cudaEventCreateWithFlags(&eCvtX, cudaEventDisableTiming);
        cudaEventCreateWithFlags(&eW1a,  cudaEventDisableTiming);
        cudaEventCreateWithFlags(&eScan, cudaEventDisableTiming);
        cudaEventCreateWithFlags(&eG1a,  cudaEventDisableTiming);
        cudaEventCreateWithFlags(&eG1b,  cudaEventDisableTiming);
        cudaEventCreateWithFlags(&eCvt2, cudaEventDisableTiming);
        cudaEventCreateWithFlags(&eG2a,  cudaEventDisableTiming);
    }

    const int halfW = NEXP * FDIM * DDIM / 2;   // elements in 8 experts of W1/W2

    // --- fork immediately ---
    zero_cnt_kernel<<<1, 32>>>(out_ent);
    cudaEventRecord(eFork, 0);
    cudaStreamWaitEvent(s1, eFork, 0);
    cudaStreamWaitEvent(s2, eFork, 0);

    // s1: W1 in expert halves, then G1b runs right here (no dependence on G1a)
    cvt_kernel<<<2048, 256, 0, s1>>>(W1, w1h_p, halfW / 8);
    cudaEventRecord(eW1a, s1);
    cvt_kernel<<<2048, 256, 0, s1>>>(W1 + halfW, w1h_p + halfW, halfW / 8);

    // s2: x (tiny) -> out memset -> W2
    cvt_kernel<<<512, 256, 0, s2>>>(x, xh_p, NTOK * DDIM / 8);
    cudaEventRecord(eCvtX, s2);
    cudaMemsetAsync(out, 0, (size_t)NTOK * DDIM * sizeof(float), s2);
    cvt_kernel<<<2048, 256, 0, s2>>>(W2, w2h_p, NEXP * DDIM * FDIM / 8);
    cudaEventRecord(eCvt2, s2);

    // stream 0: routing + scan
    routing_kernel<<<(NTOK * 32 + 255) / 256, 256>>>(x, Wg, We, out_logits, out_ent);
    scan_kernel<<<1, 32>>>();
    cudaEventRecord(eScan, 0);

    dim3 g1(FDIM / BN, MTILES, NEXP / 2);
    dim3 g2(DDIM / BN, MTILES, (NEXP / 2) * 2);

    // --- G1a on stream 0: needs scan (program order) + W1 first half + xh ---
    cudaStreamWaitEvent(0, eW1a, 0);
    cudaStreamWaitEvent(0, eCvtX, 0);
    gemm_fp16<DDIM, 1, true><<<g1, NTHREADS, SM_TOTAL>>>(nullptr, 0);
    cudaEventRecord(eG1a, 0);

    // --- G1b on s1 (concurrent with G1a): needs W1 second half (program order) + scan + xh ---
    cudaStreamWaitEvent(s1, eScan, 0);
    cudaStreamWaitEvent(s1, eCvtX, 0);
    gemm_fp16<DDIM, 1, true><<<g1, NTHREADS, SM_TOTAL, s1>>>(nullptr, 8);
    cudaEventRecord(eG1b, s1);

    // --- G2a on s2: needs memset+cvt W2 (program order) + G1a ---
    cudaStreamWaitEvent(s2, eG1a, 0);
    gemm_fp16<FDIM, 2, false><<<g2, NTHREADS, SM_TOTAL, s2>>>(out, 0);
    cudaEventRecord(eG2a, s2);

    // --- G2b on stream 0: needs G1b + memset/cvt W2 ---
    cudaStreamWaitEvent(0, eG1b, 0);
    cudaStreamWaitEvent(0, eCvt2, 0);
    gemm_fp16<FDIM, 2, false><<<g2, NTHREADS, SM_TOTAL>>>(out, 8);

    // final join
    cudaStreamWaitEvent(0, eG2a, 0);
}

// round 17
// speedup vs baseline: 1.5190x; 1.0466x over previous
#include <cuda_runtime.h>
#include <cuda_fp16.h>
#include <cstdint>
#include <math.h>

// ---------------- problem constants ----------------
#define NTOK 4096      // B*T
#define DDIM 1024      // D
#define GNUM 4
#define FDIM 4096      // F
#define NEXP 16        // G*E
#define HROWS 10240    // 8192 pairs + per-expert 128-padding

// ---------------- GEMM tiling ----------------
#define BM 128
#define BN 128
#define BKH 64         // halves per K-tile (128 bytes = SW128 row)
#define STAGES 3
#define NTHREADS 256   // 8 warps (2x4), warp tile 64x32 -> 2 CTAs/SM
#define MTILES 10      // M-tiles per expert: supports cnt <= 1280 (>30 sigma of ~Bin(8192,1/16))

#define SM_TOK   0
#define SM_WT    512
#define SM_A     1024                      // STAGES x 16384
#define SM_B     (SM_A + STAGES * 16384)
#define SM_TOTAL (SM_B + STAGES * 16384)   // 99328 -> 2 CTAs/SM

// ---------------- device scratch ----------------
__device__ int    g_cnt[NEXP];
__device__ int    g_off[NEXP];
__device__ int    g_tok[NEXP][NTOK];
__device__ float  g_wt [NEXP][NTOK];
__device__ __half g_H  [(size_t)HROWS * FDIM];            // 80 MB
__device__ __half g_xh [(size_t)NTOK * DDIM];             // 8 MB
__device__ __half g_W1h[(size_t)NEXP * FDIM * DDIM];      // 128 MB
__device__ __half g_W2h[(size_t)NEXP * DDIM * FDIM];      // 128 MB

// ---------------- helpers ----------------
__device__ __forceinline__ uint32_t s2u(const void* p) {
    uint32_t a;
    asm("{ .reg .u64 t; cvta.to.shared.u64 t, %1; cvt.u32.u64 %0, t; }" : "=r"(a) : "l"(p));
    return a;
}
__device__ __forceinline__ float gelu_exact(float v) {
    return 0.5f * v * (1.0f + erff(v * 0.7071067811865476f));
}
__device__ __forceinline__ void mma_f16(float c[4], const uint32_t a[4], const uint32_t b[2]) {
    asm volatile(
        "mma.sync.aligned.m16n8k16.row.col.f32.f16.f16.f32 "
        "{%0,%1,%2,%3}, {%4,%5,%6,%7}, {%8,%9}, {%0,%1,%2,%3};\n"
        : "+f"(c[0]), "+f"(c[1]), "+f"(c[2]), "+f"(c[3])
        : "r"(a[0]), "r"(a[1]), "r"(a[2]), "r"(a[3]), "r"(b[0]), "r"(b[1]));
}
__device__ __forceinline__ void ldsm4(uint32_t r[4], uint32_t addr) {
    asm volatile("ldmatrix.sync.aligned.m8n8.x4.shared.b16 {%0,%1,%2,%3}, [%4];"
        : "=r"(r[0]), "=r"(r[1]), "=r"(r[2]), "=r"(r[3]) : "r"(addr));
}
#define CP_ASYNC16(dst, src) \
    asm volatile("cp.async.cg.shared.global [%0], [%1], 16;" :: "r"(dst), "l"(src) : "memory")
#define CP_COMMIT() asm volatile("cp.async.commit_group;" ::: "memory")
#define CP_WAIT(n)  asm volatile("cp.async.wait_group %0;" :: "n"(n) : "memory")

// ---------------- kernel: f32 -> f16 conversion (prepass) ----------------
__global__ void cvt_kernel(const float* __restrict__ src, __half* __restrict__ dst, int n8) {
    int i = blockIdx.x * blockDim.x + threadIdx.x;
    int stride = gridDim.x * blockDim.x;
    for (; i < n8; i += stride) {
        const float4* s = (const float4*)src + (size_t)i * 2;
        float4 a = s[0], b = s[1];
        __half2 h0 = __floats2half2_rn(a.x, a.y);
        __half2 h1 = __floats2half2_rn(a.z, a.w);
        __half2 h2 = __floats2half2_rn(b.x, b.y);
        __half2 h3 = __floats2half2_rn(b.z, b.w);
        uint4 u;
        u.x = *(uint32_t*)&h0; u.y = *(uint32_t*)&h1;
        u.z = *(uint32_t*)&h2; u.w = *(uint32_t*)&h3;
        *((uint4*)dst + i) = u;
    }
}

// ---------------- kernel 0: zero expert counters + entropy slot ------------
__global__ void zero_cnt_kernel(float* __restrict__ ent) {
    if (threadIdx.x < NEXP) g_cnt[threadIdx.x] = 0;
    if (threadIdx.x == 0) *ent = 0.f;
}

// ---------------- kernel 1: routing (one warp per token, float4 loads) -----
__global__ void routing_kernel(const float* __restrict__ x,
                               const float* __restrict__ Wg,
                               const float* __restrict__ We,
                               float* __restrict__ out_logits,
                               float* __restrict__ out_ent) {
    int warp = (blockIdx.x * blockDim.x + threadIdx.x) >> 5;
    int lane = threadIdx.x & 31;
    if (warp >= NTOK) return;

    const float4* xr  = (const float4*)(x + (size_t)warp * DDIM);
    const float4* Wg4 = (const float4*)Wg;
    const float4* We4 = (const float4*)We;

    float acc[20];
#pragma unroll
    for (int j = 0; j < 20; j++) acc[j] = 0.f;

#pragma unroll
    for (int it = 0; it < DDIM / 4 / 32; it++) {     // 8 iterations
        int k4 = it * 32 + lane;
        float4 xv = xr[k4];
#pragma unroll
        for (int g = 0; g < GNUM; g++) {
            float4 w = Wg4[g * (DDIM / 4) + k4];
            acc[g] += xv.x * w.x + xv.y * w.y + xv.z * w.z + xv.w * w.w;
        }
#pragma unroll
        for (int j = 0; j < NEXP; j++) {
            float4 w = We4[j * (DDIM / 4) + k4];
            acc[4 + j] += xv.x * w.x + xv.y * w.y + xv.z * w.z + xv.w * w.w;
        }
    }
#pragma unroll
    for (int o = 16; o > 0; o >>= 1) {
#pragma unroll
        for (int j = 0; j < 20; j++) acc[j] += __shfl_xor_sync(0xFFFFFFFFu, acc[j], o);
    }

    if (lane == 0) {
        float gl[4] = {acc[0], acc[1], acc[2], acc[3]};
#pragma unroll
        for (int g = 0; g < 4; g++) out_logits[warp * 4 + g] = gl[g];

        float mx = fmaxf(fmaxf(gl[0], gl[1]), fmaxf(gl[2], gl[3]));
        float ex4[4], s = 0.f;
#pragma unroll
        for (int g = 0; g < 4; g++) { ex4[g] = expf(gl[g] - mx); s += ex4[g]; }
        float ls = logf(s);
        float ent = 0.f;
#pragma unroll
        for (int g = 0; g < 4; g++) {
            float p = ex4[g] / s;
            ent -= p * (gl[g] - mx - ls);
        }
        atomicAdd(out_ent, ent * (1.0f / NTOK));

        int g0 = 0;
#pragma unroll
        for (int g = 1; g < 4; g++) if (gl[g] > gl[g0]) g0 = g;
        int g1 = -1;
#pragma unroll
        for (int g = 0; g < 4; g++) {
            if (g == g0) continue;
            if (g1 < 0 || gl[g] > gl[g1]) g1 = g;
        }
        float w0 = 1.f / (1.f + expf(gl[g1] - gl[g0]));
        float w1 = 1.f - w0;

        int   gs[2] = {g0, g1};
        float ws[2] = {w0, w1};
#pragma unroll
        for (int i = 0; i < 2; i++) {
            int g = gs[i];
            int eb = 4 + g * 4;
            int e = 0;
#pragma unroll
            for (int e2 = 1; e2 < 4; e2++) if (acc[eb + e2] > acc[eb + e]) e = e2;
            int exid = g * 4 + e;
            int slot = atomicAdd(&g_cnt[exid], 1);
            g_tok[exid][slot] = warp;
            g_wt[exid][slot]  = ws[i];
        }
    }
}

// ---------------- kernel 2: 16-entry padded prefix scan ----------------
__global__ void scan_kernel() {
    if (threadIdx.x == 0) {
        int o = 0;
        for (int e = 0; e < NEXP; e++) {
            g_off[e] = o;
            o += (g_cnt[e] + 127) & ~127;
        }
    }
}

// ---------------- fp16 tensor-core GEMM ----------------
// C[m,n] = sum_k A[m,k]*B[n,k]  (both K-contiguous fp16 in gmem)
// FIRST=true : A = gathered x (fp16), B = W1h[ex], epilogue gelu -> g_H (fp16)
// FIRST=false: A = g_H rows,         B = W2h[ex], epilogue w * atomicAdd -> out (f32)
// 256 threads = 8 warps (2x4), warp tile 64x32, mma.m16n8k16, 2 CTAs/SM
template <int KH, int SPLITK, bool FIRST>
__global__ void __launch_bounds__(NTHREADS, 2)
gemm_fp16(float* __restrict__ OUT, int zbase) {
    extern __shared__ char smem[];
    const int ex  = zbase + (int)blockIdx.z / SPLITK;
    const int ks  = (int)blockIdx.z % SPLITK;
    const int cnt = g_cnt[ex];
    const int m0  = blockIdx.y * BM;
    if (m0 >= cnt) return;
    const int n0  = blockIdx.x * BN;
    const int KHS = KH / SPLITK;
    const int kof = ks * KHS;

    const int tid  = threadIdx.x;
    const int wid  = tid >> 5;
    const int lane = tid & 31;
    const uint32_t sb = s2u(smem);

    int*   s_tok = (int*)(smem + SM_TOK);
    float* s_wt  = (float*)(smem + SM_WT);
    if (tid < BM) {
        int m  = m0 + tid;
        int mm = (m < cnt) ? m : (cnt - 1);
        s_tok[tid] = g_tok[ex][mm];
        s_wt[tid]  = (m < cnt) ? g_wt[ex][m] : 0.f;
    }
    __syncthreads();

    // ---- cp.async chunk assignment (16B chunks, SW128 swizzled dst) ----
    const __half* aSrc[4]; uint32_t aDst[4];
#pragma unroll
    for (int i = 0; i < 4; i++) {
        int c = tid + i * NTHREADS, r = c >> 3, u = c & 7;
        const __half* rowp;
        if (FIRST) rowp = g_xh + (size_t)s_tok[r] * DDIM;
        else       rowp = g_H  + (size_t)(g_off[ex] + m0 + r) * FDIM;
        aSrc[i] = rowp + kof + u * 8;
        aDst[i] = sb + SM_A + r * 128 + ((u ^ (r & 7)) << 4);
    }
    const __half* bSrc[4]; uint32_t bDst[4];
    const __half* Wb = (FIRST ? g_W1h : g_W2h) + (size_t)ex * ((size_t)FDIM * DDIM);
#pragma unroll
    for (int i = 0; i < 4; i++) {
        int c = tid + i * NTHREADS, r = c >> 3, u = c & 7;
        bSrc[i] = Wb + (size_t)(n0 + r) * KH + kof + u * 8;
        bDst[i] = sb + SM_B + r * 128 + ((u ^ (r & 7)) << 4);
    }

    auto issue_stage = [&](int kt, int s) {
        const uint32_t off = (uint32_t)s * 16384u;
#pragma unroll
        for (int i = 0; i < 4; i++) CP_ASYNC16(aDst[i] + off, aSrc[i] + (size_t)kt * BKH);
#pragma unroll
        for (int i = 0; i < 4; i++) CP_ASYNC16(bDst[i] + off, bSrc[i] + (size_t)kt * BKH);
        CP_COMMIT();
    };

    // ---- warp / lane geometry (2x4 warps, 64x32 each) ----
    const int wm = wid >> 2;                 // 0..1: 64-row block
    const int wn = wid & 3;                  // 0..3: 32-col block
    const int laRow = lane & 15;
    const int laDu  = (lane >> 4) & 1;
    const int lbRow = (lane & 7) + ((lane & 16) >> 1);
    const int lbDu  = (lane >> 3) & 1;

    float acc[4][4][4];
#pragma unroll
    for (int i = 0; i < 4; i++)
#pragma unroll
        for (int j = 0; j < 4; j++)
#pragma unroll
            for (int r = 0; r < 4; r++) acc[i][j][r] = 0.f;

    const int NKT = KHS / BKH;

    issue_stage(0, 0);
    issue_stage(1, 1);

    for (int kt = 0; kt < NKT; kt++) {
        if (kt + 1 < NKT) { CP_WAIT(1); } else { CP_WAIT(0); }
        __syncthreads();
        // safe post-barrier prefetch: stage (kt+2)%3 was last read in iter kt-1
        if (kt + 2 < NKT) issue_stage(kt + 2, (kt + 2) % STAGES);

        const int s = kt % STAGES;
        const uint32_t As = sb + SM_A + s * 16384;
        const uint32_t Bs = sb + SM_B + s * 16384;

#pragma unroll
        for (int kk8 = 0; kk8 < 8; kk8 += 2) {   // 4 kk16 steps per K-tile
            uint32_t afr[4][4], bfr[4][2];
#pragma unroll
            for (int fm = 0; fm < 4; fm++) {
                int r = wm * 64 + fm * 16 + laRow;
                int u = kk8 + laDu;
                ldsm4(afr[fm], As + r * 128 + ((u ^ (r & 7)) << 4));
            }
#pragma unroll
            for (int fp = 0; fp < 2; fp++) {
                int r = wn * 32 + fp * 16 + lbRow;
                int u = kk8 + lbDu;
                uint32_t q[4];
                ldsm4(q, Bs + r * 128 + ((u ^ (r & 7)) << 4));
                bfr[2 * fp][0] = q[0]; bfr[2 * fp][1] = q[1];
                bfr[2 * fp + 1][0] = q[2]; bfr[2 * fp + 1][1] = q[3];
            }
#pragma unroll
            for (int fm = 0; fm < 4; fm++)
#pragma unroll
                for (int fn = 0; fn < 4; fn++)
                    mma_f16(acc[fm][fn], afr[fm], bfr[fn]);
        }
        // no trailing barrier: next iteration's top barrier fences reuse
    }

    // ---------------- epilogue ----------------
    const int er = lane >> 2;
    const int ec = (lane & 3) * 2;
    if (FIRST) {
        const int hb = g_off[ex];
#pragma unroll
        for (int fm = 0; fm < 4; fm++) {
#pragma unroll
            for (int hh = 0; hh < 2; hh++) {
                int mloc = wm * 64 + fm * 16 + er + hh * 8;
                int m = m0 + mloc;
                if (m < cnt) {
                    __half* dst = g_H + (size_t)(hb + m) * FDIM + n0 + wn * 32 + ec;
#pragma unroll
                    for (int fn = 0; fn < 4; fn++) {
                        float v0 = gelu_exact(acc[fm][fn][hh * 2 + 0]);
                        float v1 = gelu_exact(acc[fm][fn][hh * 2 + 1]);
                        *(__half2*)(dst + fn * 8) = __floats2half2_rn(v0, v1);
                    }
                }
            }
        }
    } else {
#pragma unroll
        for (int fm = 0; fm < 4; fm++) {
#pragma unroll
            for (int hh = 0; hh < 2; hh++) {
                int mloc = wm * 64 + fm * 16 + er + hh * 8;
                int m = m0 + mloc;
                if (m < cnt) {
                    int   tok = s_tok[mloc];
                    float w   = s_wt[mloc];
                    float* dst = OUT + (size_t)tok * DDIM + n0 + wn * 32 + ec;
#pragma unroll
                    for (int fn = 0; fn < 4; fn++) {
                        atomicAdd(dst + fn * 8 + 0, w * acc[fm][fn][hh * 2 + 0]);
                        atomicAdd(dst + fn * 8 + 1, w * acc[fm][fn][hh * 2 + 1]);
                    }
                }
            }
        }
    }
}

// ---------------- launch ----------------
extern "C" void kernel_launch(void* const* d_in, const int* in_sizes, int n_in,
                              void* d_out, int out_size) {
    const float* x  = (const float*)d_in[0];
    const float* Wg = (const float*)d_in[1];
    const float* We = (const float*)d_in[2];
    const float* W1 = (const float*)d_in[3];
    const float* W2 = (const float*)d_in[4];
    float* out = (float*)d_out;

    // output layout: [out (N*D)] [group_logits (N*G)] [group_entropy (1)]
    float* out_logits = out + (size_t)NTOK * DDIM;
    float* out_ent    = out_logits + (size_t)NTOK * GNUM;

    static __half* xh_p  = nullptr;
    static __half* w1h_p = nullptr;
    static __half* w2h_p = nullptr;
    static cudaStream_t s1, s2;
    static cudaEvent_t eFork, eCvtX, eW1a, eScan, eG1a, eG1b, eCvt2, eG2a;
    if (!xh_p) {
        cudaGetSymbolAddress((void**)&xh_p,  g_xh);
        cudaGetSymbolAddress((void**)&w1h_p, g_W1h);
        cudaGetSymbolAddress((void**)&w2h_p, g_W2h);
        cudaFuncSetAttribute((const void*)gemm_fp16<DDIM, 1, true>,
                             cudaFuncAttributeMaxDynamicSharedMemorySize, SM_TOTAL);
        cudaFuncSetAttribute((const void*)gemm_fp16<FDIM, 2, false>,
                             cudaFuncAttributeMaxDynamicSharedMemorySize, SM_TOTAL);
        cudaStreamCreateWithFlags(&s1, cudaStreamNonBlocking);
        cudaStreamCreateWithFlags(&s2, cudaStreamNonBlocking);
        cudaEventCreateWithFlags(&eFork, cudaEventDisableTiming);
        cudaEventCreateWithFlags(&eCvtX, cudaEventDisableTiming);
        cudaEventCreateWithFlags(&eW1a,  cudaEventDisableTiming);
        cudaEventCreateWithFlags(&eScan, cudaEventDisableTiming);
        cudaEventCreateWithFlags(&eG1a,  cudaEventDisableTiming);
        cudaEventCreateWithFlags(&eG1b,  cudaEventDisableTiming);
        cudaEventCreateWithFlags(&eCvt2, cudaEventDisableTiming);
        cudaEventCreateWithFlags(&eG2a,  cudaEventDisableTiming);
    }

    const int halfW = NEXP * FDIM * DDIM / 2;   // elements in 8 experts of W1/W2

    // --- fork immediately ---
    zero_cnt_kernel<<<1, 32>>>(out_ent);
    cudaEventRecord(eFork, 0);
    cudaStreamWaitEvent(s1, eFork, 0);
    cudaStreamWaitEvent(s2, eFork, 0);

    // s1: W1 in expert halves, then G1b runs right here (no dependence on G1a)
    cvt_kernel<<<2048, 256, 0, s1>>>(W1, w1h_p, halfW / 8);
    cudaEventRecord(eW1a, s1);
    cvt_kernel<<<2048, 256, 0, s1>>>(W1 + halfW, w1h_p + halfW, halfW / 8);

    // s2: x (tiny) -> out memset -> W2
    cvt_kernel<<<512, 256, 0, s2>>>(x, xh_p, NTOK * DDIM / 8);
    cudaEventRecord(eCvtX, s2);
    cudaMemsetAsync(out, 0, (size_t)NTOK * DDIM * sizeof(float), s2);
    cvt_kernel<<<2048, 256, 0, s2>>>(W2, w2h_p, NEXP * DDIM * FDIM / 8);
    cudaEventRecord(eCvt2, s2);

    // stream 0: routing + scan
    routing_kernel<<<(NTOK * 32 + 255) / 256, 256>>>(x, Wg, We, out_logits, out_ent);
    scan_kernel<<<1, 32>>>();
    cudaEventRecord(eScan, 0);

    dim3 g1(FDIM / BN, MTILES, NEXP / 2);
    dim3 g2(DDIM / BN, MTILES, (NEXP / 2) * 2);

    // --- G1a on stream 0: needs scan (program order) + W1 first half + xh ---
    cudaStreamWaitEvent(0, eW1a, 0);
    cudaStreamWaitEvent(0, eCvtX, 0);
    gemm_fp16<DDIM, 1, true><<<g1, NTHREADS, SM_TOTAL>>>(nullptr, 0);
    cudaEventRecord(eG1a, 0);

    // --- G1b on s1 (concurrent with G1a): needs W1 second half (program order) + scan + xh ---
    cudaStreamWaitEvent(s1, eScan, 0);
    cudaStreamWaitEvent(s1, eCvtX, 0);
    gemm_fp16<DDIM, 1, true><<<g1, NTHREADS, SM_TOTAL, s1>>>(nullptr, 8);
    cudaEventRecord(eG1b, s1);

    // --- G2a on s2: needs memset+cvt W2 (program order) + G1a ---
    cudaStreamWaitEvent(s2, eG1a, 0);
    gemm_fp16<FDIM, 2, false><<<g2, NTHREADS, SM_TOTAL, s2>>>(out, 0);
    cudaEventRecord(eG2a, s2);

    // --- G2b on stream 0: needs G1b + memset/cvt W2 ---
    cudaStreamWaitEvent(0, eG1b, 0);
    cudaStreamWaitEvent(0, eCvt2, 0);
    gemm_fp16<FDIM, 2, false><<<g2, NTHREADS, SM_TOTAL>>>(out, 8);

    // final join
    cudaStreamWaitEvent(0, eG2a, 0);
}